// round 12
// baseline (speedup 1.0000x reference)
#include <cuda_runtime.h>
#include <cuda_bf16.h>
#include <cstdint>

// ---------------- problem constants (fixed shapes) ----------------
#define N_NODES 200000
#define N_EDGES 1000000
#define D_NODE  128
#define D_EDGE  64
#define HDIM    256
#define NGRAPH  512

#define MTILE 64
#define NODE_TILES (N_NODES / MTILE)   // 3125 (exact)
#define EDGE_TILES (N_EDGES / MTILE)   // 15625 (exact)
#define NCTA  128                      // output columns per CTA (HDIM split in 2)

// ---------------- scratch (device globals; no allocation) ----------------
__device__ float d_S_node[NGRAPH * HDIM];
__device__ float d_S_edge[NGRAPH * HDIM];
__device__ int   d_cnt_node[NGRAPH];
__device__ int   d_cnt_edge[NGRAPH];
__device__ unsigned short d_eb[N_EDGES];     // graph id per edge
__device__ int   d_esorted[N_EDGES];         // edge ids sorted by graph
__device__ int   d_cursor[NGRAPH];
__device__ __nv_bfloat16 d_Wt_node[HDIM * D_NODE];  // [n][k]  (transposed, bf16)
__device__ __nv_bfloat16 d_Wt_edge[HDIM * D_EDGE];  // [n][k]

// ---------------- asm helpers ----------------
#define LDSM_X4(r0, r1, r2, r3, addr)                                          \
    asm volatile("ldmatrix.sync.aligned.m8n8.x4.shared.b16 {%0,%1,%2,%3}, [%4];" \
                 : "=r"(r0), "=r"(r1), "=r"(r2), "=r"(r3) : "r"(addr))

#define MMA16816(c0, c1, c2, c3, a0, a1, a2, a3, b0, b1)                       \
    asm volatile(                                                              \
        "mma.sync.aligned.m16n8k16.row.col.f32.bf16.bf16.f32 "                 \
        "{%0,%1,%2,%3}, {%4,%5,%6,%7}, {%8,%9}, {%0,%1,%2,%3};\n"              \
        : "+f"(c0), "+f"(c1), "+f"(c2), "+f"(c3)                               \
        : "r"(a0), "r"(a1), "r"(a2), "r"(a3), "r"(b0), "r"(b1))

// ---------------- launch #1: zero sums + weight transpose + histograms ----
// (count buffers pre-zeroed by cudaMemsetAsync — zeroing here would race)
__global__ void k_setup(const float* __restrict__ Wn1, const float* __restrict__ We1,
                        const int* __restrict__ batch_idx, const int* __restrict__ edge_src)
{
    const int b = blockIdx.x;
    const int tid = threadIdx.x;
    if (b < 64) {
        int i = b * 256 + tid;
        for (int j = i; j < HDIM * D_NODE; j += 64 * 256) {
            int n = j / D_NODE, k = j % D_NODE;
            d_Wt_node[j] = __float2bfloat16(Wn1[k * HDIM + n]);
        }
        for (int j = i; j < HDIM * D_EDGE; j += 64 * 256) {
            int n = j / D_EDGE, k = j % D_EDGE;
            d_Wt_edge[j] = __float2bfloat16(We1[k * HDIM + n]);
        }
    } else if (b < 128) {
        int i = (b - 64) * 256 + tid;
        for (int j = i; j < NGRAPH * HDIM; j += 64 * 256) { d_S_node[j] = 0.f; d_S_edge[j] = 0.f; }
    } else if (b < 328) {
        __shared__ int h[NGRAPH];
        for (int j = tid; j < NGRAPH; j += 256) h[j] = 0;
        __syncthreads();
        int i = (b - 128) * 256 + tid;
        for (int n = i; n < N_NODES; n += 200 * 256) atomicAdd(&h[batch_idx[n]], 1);
        __syncthreads();
        for (int j = tid; j < NGRAPH; j += 256)
            if (h[j]) atomicAdd(&d_cnt_node[j], h[j]);
    } else {
        __shared__ int h[NGRAPH];
        for (int j = tid; j < NGRAPH; j += 256) h[j] = 0;
        __syncthreads();
        int i = (b - 328) * 256 + tid;
        for (int e = i; e < N_EDGES; e += 512 * 256) {
            int g = batch_idx[edge_src[e]];
            d_eb[e] = (unsigned short)g;
            atomicAdd(&h[g], 1);
        }
        __syncthreads();
        for (int j = tid; j < NGRAPH; j += 256)
            if (h[j]) atomicAdd(&d_cnt_edge[j], h[j]);
    }
}

// ---------------- launch #2: exclusive prefix sum of edge counts ----------
__global__ void k_scan() {
    __shared__ int wsum[16];
    int tid = threadIdx.x;
    int lane = tid & 31, w = tid >> 5;
    int v = d_cnt_edge[tid];
    int s = v;
    #pragma unroll
    for (int o = 1; o < 32; o <<= 1) {
        int t = __shfl_up_sync(0xffffffffu, s, o);
        if (lane >= o) s += t;
    }
    if (lane == 31) wsum[w] = s;
    __syncthreads();
    if (tid == 0) {
        int run = 0;
        for (int i = 0; i < 16; i++) { int t = wsum[i]; wsum[i] = run; run += t; }
    }
    __syncthreads();
    d_cursor[tid] = s + wsum[w] - v;   // exclusive
}

// ---------------- launch #3: counting-sort scatter of edge ids ------------
__global__ void k_scatter() {
    int i = blockIdx.x * blockDim.x + threadIdx.x;
    int stride = gridDim.x * blockDim.x;
    for (int e = i; e < N_EDGES; e += stride) {
        int g = (int)d_eb[e];
        int p = atomicAdd(&d_cursor[g], 1);
        d_esorted[p] = e;
    }
}

// ================= launch #4: EDGE GEMM, pipelined + B-in-registers ========
// 256 threads = 8 warps, CTA tile 64 rows x 128 cols (nhalf = blockIdx&1).
// Weight fragments LDSM'd ONCE into 32 regs/thread; mainloop = 8 LDSM(A) + 32 MMA.
// Double-buffered As + register prefetch of next gather; 1 barrier per tile.
#define EKPAD 72
#define E_AS_OFF 18432                       // Ws = 128*72*2
#define E_ASB    9216                        // one As buffer = 64*72*2
#define E_GID    36864                       // 2 x 64 ints
#define E_ES     37376                       // 2 x 64 ints
#define E_BIAS   37888                       // 128 floats
#define E_SMEM   38400

__global__ void __launch_bounds__(256, 2)
k_gemm_edge(const float* __restrict__ edge_attr, const float* __restrict__ be1)
{
    extern __shared__ char smem[];
    uint32_t sbase = (uint32_t)__cvta_generic_to_shared(smem);
    __nv_bfloat16* Ws = (__nv_bfloat16*)smem;
    __nv_bfloat16* As = (__nv_bfloat16*)(smem + E_AS_OFF);  // [2][64*72]
    int*   gid_s  = (int*)(smem + E_GID);                   // [2][64]
    int*   es_s   = (int*)(smem + E_ES);                    // [2][64]
    float* bias_s = (float*)(smem + E_BIAS);

    const int tid = threadIdx.x;
    const int nbase = (blockIdx.x & 1) * NCTA;   // grid stride even -> fixed per CTA

    // weights [n][k], k=64 padded to 72
    const uint32_t* Wg32 = (const uint32_t*)d_Wt_edge;
    for (int j = tid; j < NCTA * 32; j += 256) {
        int n = j >> 5, k2 = j & 31;
        *(uint32_t*)&Ws[n * EKPAD + 2 * k2] = Wg32[(nbase + n) * 32 + k2];
    }
    if (tid < NCTA) bias_s[tid] = be1[nbase + tid];

    const int lane = tid & 31, warp = tid >> 5;
    const int wm = (warp & 1) * 32;
    const int wn = (warp >> 1) * 32;
    const int gID = lane >> 2, tig = lane & 3;

    const uint32_t a_off = (uint32_t)(((wm + (lane & 15)) * EKPAD + ((lane >> 4) << 3)) * 2);
    const int brow = (lane & 7) + ((lane >> 4) << 3);
    const int bkof = ((lane >> 3) & 1) << 3;
    const uint32_t b_addr0 = sbase + (uint32_t)(((wn + brow) * EKPAD + bkof) * 2);

    // gather index decomposition: j = tid + i*256 -> r = (tid>>4) + 16i, q = tid&15
    const int grow = tid >> 4;
    const int gq   = tid & 15;

    const int NB = 2 * EDGE_TILES;     // 31250
    const int stride = gridDim.x;

    // ---- prologue: stage first tile into buffer 0 ----
    {
        int r0 = (blockIdx.x >> 1) * MTILE;
        if (tid < MTILE) {
            int e = d_esorted[r0 + tid];
            es_s[tid]  = e;
            gid_s[tid] = (int)d_eb[e];
        }
    }
    __syncthreads();   // Ws + bias + first indices visible

    // ---- load ALL weight fragments into registers (fixed for whole kernel) ----
    uint32_t breg[4][2][4];   // [kstep][nfp][b0,b1,b2,b3]
    #pragma unroll
    for (int ks = 0; ks < 4; ks++)
        #pragma unroll
        for (int nfp = 0; nfp < 2; nfp++)
            LDSM_X4(breg[ks][nfp][0], breg[ks][nfp][1], breg[ks][nfp][2], breg[ks][nfp][3],
                    b_addr0 + (uint32_t)(nfp * 16 * EKPAD * 2) + (uint32_t)(ks * 32));

    int gr0c[2], gr1c[2];
    gr0c[0] = gid_s[wm + gID];       gr0c[1] = gid_s[wm + 16 + gID];
    gr1c[0] = gid_s[wm + gID + 8];   gr1c[1] = gid_s[wm + 16 + gID + 8];
    int glo_c = gid_s[0], ghi_c = gid_s[MTILE - 1];
    {
        float4 v[4];
        #pragma unroll
        for (int i = 0; i < 4; i++)
            v[i] = *(const float4*)(edge_attr + (size_t)es_s[grow + 16 * i] * 64 + gq * 4);
        #pragma unroll
        for (int i = 0; i < 4; i++) {
            __nv_bfloat162 p0 = __float22bfloat162_rn(make_float2(v[i].x, v[i].y));
            __nv_bfloat162 p1 = __float22bfloat162_rn(make_float2(v[i].z, v[i].w));
            uint2 pk; pk.x = *(uint32_t*)&p0; pk.y = *(uint32_t*)&p1;
            *(uint2*)&As[(grow + 16 * i) * EKPAD + gq * 4] = pk;
        }
    }

    int p = 0;
    for (int b = blockIdx.x; b < NB; b += stride) {
        const int q = p ^ 1;
        const int bn = b + stride;
        const bool has_next = (bn < NB);

        // stage next tile's indices into buffer q (before the barrier)
        if (has_next && tid < MTILE) {
            int r0n = (bn >> 1) * MTILE;
            int e = d_esorted[r0n + tid];
            es_s[q * MTILE + tid]  = e;
            gid_s[q * MTILE + tid] = (int)d_eb[e];
        }
        __syncthreads();   // As[p] (prev STS) + es/gid[q] visible; all reads of As[q] done

        // prefetch next tile's gid fragments into registers
        int gr0n[2] = {0, 0}, gr1n[2] = {0, 0}, glo_n = 0, ghi_n = -1;
        if (has_next) {
            gr0n[0] = gid_s[q * MTILE + wm + gID];
            gr0n[1] = gid_s[q * MTILE + wm + 16 + gID];
            gr1n[0] = gid_s[q * MTILE + wm + gID + 8];
            gr1n[1] = gid_s[q * MTILE + wm + 16 + gID + 8];
            glo_n = gid_s[q * MTILE];
            ghi_n = gid_s[q * MTILE + MTILE - 1];
        }

        // issue next tile's gather LDGs (results land after the MMA below)
        float4 v[4];
        if (has_next) {
            #pragma unroll
            for (int i = 0; i < 4; i++)
                v[i] = *(const float4*)(edge_attr +
                        (size_t)es_s[q * MTILE + grow + 16 * i] * 64 + gq * 4);
        }

        // ---- mainloop on As[p]: A-LDSM + MMA only ----
        const uint32_t a_base = sbase + E_AS_OFF + (uint32_t)(p * E_ASB) + a_off;
        float c[2][4][4];
        #pragma unroll
        for (int mf = 0; mf < 2; mf++)
            #pragma unroll
            for (int nf = 0; nf < 4; nf++)
                #pragma unroll
                for (int r = 0; r < 4; r++) c[mf][nf][r] = 0.f;

        #pragma unroll
        for (int ks = 0; ks < 4; ks++) {
            const uint32_t koff = (uint32_t)(ks * 32);
            uint32_t a[2][4];
            LDSM_X4(a[0][0], a[0][1], a[0][2], a[0][3], a_base + koff);
            LDSM_X4(a[1][0], a[1][1], a[1][2], a[1][3], a_base + 16 * EKPAD * 2 + koff);
            #pragma unroll
            for (int nfp = 0; nfp < 2; nfp++) {
                const int nf = 2 * nfp;
                MMA16816(c[0][nf][0], c[0][nf][1], c[0][nf][2], c[0][nf][3],
                         a[0][0], a[0][1], a[0][2], a[0][3],
                         breg[ks][nfp][0], breg[ks][nfp][1]);
                MMA16816(c[1][nf][0], c[1][nf][1], c[1][nf][2], c[1][nf][3],
                         a[1][0], a[1][1], a[1][2], a[1][3],
                         breg[ks][nfp][0], breg[ks][nfp][1]);
                MMA16816(c[0][nf+1][0], c[0][nf+1][1], c[0][nf+1][2], c[0][nf+1][3],
                         a[0][0], a[0][1], a[0][2], a[0][3],
                         breg[ks][nfp][2], breg[ks][nfp][3]);
                MMA16816(c[1][nf+1][0], c[1][nf+1][1], c[1][nf+1][2], c[1][nf+1][3],
                         a[1][0], a[1][1], a[1][2], a[1][3],
                         breg[ks][nfp][2], breg[ks][nfp][3]);
            }
        }

        // ---- bias + relu ----
        #pragma unroll
        for (int nf = 0; nf < 4; nf++) {
            float b0 = bias_s[wn + nf * 8 + 2 * tig];
            float b1 = bias_s[wn + nf * 8 + 2 * tig + 1];
            #pragma unroll
            for (int mf = 0; mf < 2; mf++) {
                c[mf][nf][0] = fmaxf(c[mf][nf][0] + b0, 0.f);
                c[mf][nf][1] = fmaxf(c[mf][nf][1] + b1, 0.f);
                c[mf][nf][2] = fmaxf(c[mf][nf][2] + b0, 0.f);
                c[mf][nf][3] = fmaxf(c[mf][nf][3] + b1, 0.f);
            }
        }

        // ---- per-graph register reduce + global atomics ----
        for (int g = glo_c; g <= ghi_c; ++g) {
            #pragma unroll
            for (int nf = 0; nf < 4; nf++) {
                float s0 = 0.f, s1 = 0.f;
                #pragma unroll
                for (int mf = 0; mf < 2; mf++) {
                    if (gr0c[mf] == g) { s0 += c[mf][nf][0]; s1 += c[mf][nf][1]; }
                    if (gr1c[mf] == g) { s0 += c[mf][nf][2]; s1 += c[mf][nf][3]; }
                }
                #pragma unroll
                for (int o = 4; o <= 16; o <<= 1) {
                    s0 += __shfl_xor_sync(0xffffffffu, s0, o);
                    s1 += __shfl_xor_sync(0xffffffffu, s1, o);
                }
                if (lane < 4) {
                    float* dst = &d_S_edge[g * HDIM + nbase + wn + nf * 8 + 2 * lane];
                    atomicAdd(dst,     s0);
                    atomicAdd(dst + 1, s1);
                }
            }
        }

        // ---- store prefetched tile into As[q] ----
        if (has_next) {
            #pragma unroll
            for (int i = 0; i < 4; i++) {
                __nv_bfloat162 p0 = __float22bfloat162_rn(make_float2(v[i].x, v[i].y));
                __nv_bfloat162 p1 = __float22bfloat162_rn(make_float2(v[i].z, v[i].w));
                uint2 pk; pk.x = *(uint32_t*)&p0; pk.y = *(uint32_t*)&p1;
                *(uint2*)&As[q * (E_ASB / 2) + (grow + 16 * i) * EKPAD + gq * 4] = pk;
            }
        }

        gr0c[0] = gr0n[0]; gr0c[1] = gr0n[1];
        gr1c[0] = gr1n[0]; gr1c[1] = gr1n[1];
        glo_c = glo_n; ghi_c = ghi_n;
        p = q;
    }
}

// ================= launch #5: NODE GEMM (R7 config, measured 70.9us) ======
template<int K, int KPAD, int KSTEPS, int NITER>
__device__ __forceinline__ void node_gemm_phase(
    const float* __restrict__ A_gmem, const float* __restrict__ bias_g,
    const __nv_bfloat16* __restrict__ Wt_g,
    const int* __restrict__ batch_idx, int n_tiles,
    float* __restrict__ S_out, char* smem, uint32_t sbase)
{
    constexpr int WS_BYTES = NCTA * KPAD * 2;
    constexpr int AS_BYTES = MTILE * KPAD * 2;
    __nv_bfloat16* Ws = (__nv_bfloat16*)(smem);
    __nv_bfloat16* As = (__nv_bfloat16*)(smem + WS_BYTES);
    int*   gid_s  = (int*)(smem + WS_BYTES + AS_BYTES);
    float* bias_s = (float*)(smem + WS_BYTES + AS_BYTES + 512);

    const int tid = threadIdx.x;
    const int nbase = (blockIdx.x & 1) * NCTA;

    const uint32_t* Wg32 = (const uint32_t*)Wt_g;
    for (int j = tid; j < NCTA * K / 2; j += 256) {
        int n = j / (K / 2), k2 = j % (K / 2);
        *(uint32_t*)&Ws[n * KPAD + 2 * k2] = Wg32[(nbase + n) * (K / 2) + k2];
    }
    if (tid < NCTA) bias_s[tid] = bias_g[nbase + tid];
    __syncthreads();

    const int lane = tid & 31, warp = tid >> 5;
    const int wm = (warp & 1) * 32;
    const int wn = (warp >> 1) * 32;
    const int gID = lane >> 2, tig = lane & 3;

    const uint32_t a_addr0 = sbase + WS_BYTES +
        (uint32_t)(((wm + (lane & 15)) * KPAD + ((lane >> 4) << 3)) * 2);
    const uint32_t a_addr1 = a_addr0 + (uint32_t)(16 * KPAD * 2);
    const int brow = (lane & 7) + ((lane >> 4) << 3);
    const int bkof = ((lane >> 3) & 1) << 3;
    const uint32_t b_addr0 = sbase +
        (uint32_t)(((wn + brow) * KPAD + bkof) * 2);

    const int QK = K / 4;

    for (int b = blockIdx.x; b < 2 * n_tiles; b += gridDim.x) {
        const int t = b >> 1;
        const int r0 = t * MTILE;

        __syncthreads();
        if (tid < MTILE) gid_s[tid] = batch_idx[r0 + tid];
        __syncthreads();

        #pragma unroll
        for (int base = 0; base < NITER; base += 4) {
            float4 v[4];
            #pragma unroll
            for (int i = 0; i < 4; i++) {
                int j = tid + (base + i) * 256;
                int r = j / QK, q = j % QK;
                v[i] = *(const float4*)(A_gmem + (size_t)(r0 + r) * K + q * 4);
            }
            #pragma unroll
            for (int i = 0; i < 4; i++) {
                int j = tid + (base + i) * 256;
                int r = j / QK, q = j % QK;
                __nv_bfloat162 p0 = __float22bfloat162_rn(make_float2(v[i].x, v[i].y));
                __nv_bfloat162 p1 = __float22bfloat162_rn(make_float2(v[i].z, v[i].w));
                *(__nv_bfloat162*)&As[r * KPAD + q * 4]     = p0;
                *(__nv_bfloat162*)&As[r * KPAD + q * 4 + 2] = p1;
            }
        }
        __syncthreads();

        int gr0[2], gr1[2];
        #pragma unroll
        for (int mf = 0; mf < 2; mf++) {
            gr0[mf] = gid_s[wm + mf * 16 + gID];
            gr1[mf] = gid_s[wm + mf * 16 + gID + 8];
        }
        const int g_lo = gid_s[0];
        const int g_hi = gid_s[MTILE - 1];

        float c[2][4][4];
        #pragma unroll
        for (int mf = 0; mf < 2; mf++)
            #pragma unroll
            for (int nf = 0; nf < 4; nf++)
                #pragma unroll
                for (int r = 0; r < 4; r++) c[mf][nf][r] = 0.f;

        #pragma unroll
        for (int ks = 0; ks < KSTEPS; ks++) {
            const uint32_t koff = (uint32_t)(ks * 16 * 2);
            uint32_t a[2][4];
            LDSM_X4(a[0][0], a[0][1], a[0][2], a[0][3], a_addr0 + koff);
            LDSM_X4(a[1][0], a[1][1], a[1][2], a[1][3], a_addr1 + koff);
            #pragma unroll
            for (int nfp = 0; nfp < 2; nfp++) {
                uint32_t b0, b1, b2, b3;
                LDSM_X4(b0, b1, b2, b3,
                        b_addr0 + (uint32_t)(nfp * 16 * KPAD * 2) + koff);
                const int nf = 2 * nfp;
                MMA16816(c[0][nf][0], c[0][nf][1], c[0][nf][2], c[0][nf][3],
                         a[0][0], a[0][1], a[0][2], a[0][3], b0, b1);
                MMA16816(c[1][nf][0], c[1][nf][1], c[1][nf][2], c[1][nf][3],
                         a[1][0], a[1][1], a[1][2], a[1][3], b0, b1);
                MMA16816(c[0][nf+1][0], c[0][nf+1][1], c[0][nf+1][2], c[0][nf+1][3],
                         a[0][0], a[0][1], a[0][2], a[0][3], b2, b3);
                MMA16816(c[1][nf+1][0], c[1][nf+1][1], c[1][nf+1][2], c[1][nf+1][3],
                         a[1][0], a[1][1], a[1][2], a[1][3], b2, b3);
            }
        }

        #pragma unroll
        for (int nf = 0; nf < 4; nf++) {
            float b0 = bias_s[wn + nf * 8 + 2 * tig];
            float b1 = bias_s[wn + nf * 8 + 2 * tig + 1];
            #pragma unroll
            for (int mf = 0; mf < 2; mf++) {
                c[mf][nf][0] = fmaxf(c[mf][nf][0] + b0, 0.f);
                c[mf][nf][1] = fmaxf(c[mf][nf][1] + b1, 0.f);
                c[mf][nf][2] = fmaxf(c[mf][nf][2] + b0, 0.f);
                c[mf][nf][3] = fmaxf(c[mf][nf][3] + b1, 0.f);
            }
        }

        for (int g = g_lo; g <= g_hi; ++g) {
            #pragma unroll
            for (int nf = 0; nf < 4; nf++) {
                float s0 = 0.f, s1 = 0.f;
                #pragma unroll
                for (int mf = 0; mf < 2; mf++) {
                    if (gr0[mf] == g) { s0 += c[mf][nf][0]; s1 += c[mf][nf][1]; }
                    if (gr1[mf] == g) { s0 += c[mf][nf][2]; s1 += c[mf][nf][3]; }
                }
                #pragma unroll
                for (int o = 4; o <= 16; o <<= 1) {
                    s0 += __shfl_xor_sync(0xffffffffu, s0, o);
                    s1 += __shfl_xor_sync(0xffffffffu, s1, o);
                }
                if (lane < 4) {
                    float* dst = &S_out[g * HDIM + nbase + wn + nf * 8 + 2 * lane];
                    atomicAdd(dst,     s0);
                    atomicAdd(dst + 1, s1);
                }
            }
        }
    }
}

#define SMEM_NODE ((NCTA + MTILE) * (D_NODE + 8) * 2 + 1024)   // 53248

__global__ void __launch_bounds__(256, 4)
k_gemm_node(const float* __restrict__ x, const int* __restrict__ batch_idx,
            const float* __restrict__ bn1)
{
    extern __shared__ char smem[];
    uint32_t sbase = (uint32_t)__cvta_generic_to_shared(smem);
    node_gemm_phase<D_NODE, D_NODE + 8, D_NODE / 16, MTILE * (D_NODE / 4) / 256>(
        x, bn1, d_Wt_node, batch_idx, NODE_TILES, d_S_node, smem, sbase);
}

// ---------------- launch #6: means -> layer-2 -> combine ------------------
__global__ void __launch_bounds__(256)
k_finalize(const float* __restrict__ Wn2, const float* __restrict__ bn2,
           const float* __restrict__ We2, const float* __restrict__ be2,
           const float* __restrict__ Wc,  const float* __restrict__ bc,
           float* __restrict__ out)
{
    __shared__ float mn[8][HDIM], me[8][HDIM], gr[8][HDIM];
    __shared__ int fn[8], fe[8];
    const int tid = threadIdx.x;
    const int gbase = blockIdx.x * 8;

    #pragma unroll
    for (int gg = 0; gg < 8; gg++) {
        int g = gbase + gg;
        int cn = d_cnt_node[g], ce = d_cnt_edge[g];
        if (tid == 0) { fn[gg] = cn; fe[gg] = ce; }
        mn[gg][tid] = (cn > 0) ? d_S_node[g * HDIM + tid] / (float)cn : 0.f;
        me[gg][tid] = (ce > 0) ? d_S_edge[g * HDIM + tid] / (float)ce : 0.f;
    }
    __syncthreads();

    float an[8], ae[8];
    #pragma unroll
    for (int gg = 0; gg < 8; gg++) { an[gg] = 0.f; ae[gg] = 0.f; }
    for (int j = 0; j < HDIM; j++) {
        float w1 = Wn2[j * HDIM + tid];
        float w2 = We2[j * HDIM + tid];
        #pragma unroll
        for (int gg = 0; gg < 8; gg++) {
            an[gg] += mn[gg][j] * w1;
            ae[gg] += me[gg][j] * w2;
        }
    }
    float b2n = bn2[tid], b2e = be2[tid];
    #pragma unroll
    for (int gg = 0; gg < 8; gg++) {
        float nr = (fn[gg] > 0) ? an[gg] + b2n : 0.f;
        float er = (fe[gg] > 0) ? ae[gg] + b2e : 0.f;
        gr[gg][tid] = nr + er;
    }
    __syncthreads();

    float ao[8];
    #pragma unroll
    for (int gg = 0; gg < 8; gg++) ao[gg] = 0.f;
    for (int j = 0; j < HDIM; j++) {
        float w = Wc[j * HDIM + tid];
        #pragma unroll
        for (int gg = 0; gg < 8; gg++) ao[gg] += gr[gg][j] * w;
    }
    float bcv = bc[tid];
    #pragma unroll
    for (int gg = 0; gg < 8; gg++)
        out[(gbase + gg) * HDIM + tid] = ao[gg] + bcv;
}

// ---------------- launch ----------------
extern "C" void kernel_launch(void* const* d_in, const int* in_sizes, int n_in,
                              void* d_out, int out_size)
{
    const float* x         = (const float*)d_in[0];
    const float* edge_attr = (const float*)d_in[1];
    const int*   batch_idx = (const int*)d_in[2];
    const int*   edge_src  = (const int*)d_in[3];
    const float* Wn1 = (const float*)d_in[4];
    const float* bn1 = (const float*)d_in[5];
    const float* Wn2 = (const float*)d_in[6];
    const float* bn2 = (const float*)d_in[7];
    const float* We1 = (const float*)d_in[8];
    const float* be1 = (const float*)d_in[9];
    const float* We2 = (const float*)d_in[10];
    const float* be2 = (const float*)d_in[11];
    const float* Wc  = (const float*)d_in[12];
    const float* bc  = (const float*)d_in[13];
    float* out = (float*)d_out;

    (void)in_sizes; (void)n_in; (void)out_size;

    cudaFuncSetAttribute(k_gemm_node, cudaFuncAttributeMaxDynamicSharedMemorySize, SMEM_NODE);
    cudaFuncSetAttribute(k_gemm_edge, cudaFuncAttributeMaxDynamicSharedMemorySize, E_SMEM);

    // zero the histogram counters before k_setup's atomics
    void* p_cn = nullptr; void* p_ce = nullptr;
    cudaGetSymbolAddress(&p_cn, d_cnt_node);
    cudaGetSymbolAddress(&p_ce, d_cnt_edge);
    cudaMemsetAsync(p_cn, 0, NGRAPH * sizeof(int));
    cudaMemsetAsync(p_ce, 0, NGRAPH * sizeof(int));

    k_setup<<<840, 256>>>(Wn1, We1, batch_idx, edge_src);              // kernel #1
    k_scan<<<1, 512>>>();                                              // #2
    k_scatter<<<512, 256>>>();                                         // #3
    k_gemm_edge<<<296, 256, E_SMEM>>>(edge_attr, be1);                 // #4 (profiled slot)
    k_gemm_node<<<592, 256, SMEM_NODE>>>(x, batch_idx, bn1);           // #5
    k_finalize<<<64, 256>>>(Wn2, bn2, We2, be2, Wc, bc, out);          // #6
}

// round 13
// speedup vs baseline: 1.1750x; 1.1750x over previous
#include <cuda_runtime.h>
#include <cuda_bf16.h>
#include <cstdint>

// ---------------- problem constants (fixed shapes) ----------------
#define N_NODES 200000
#define N_EDGES 1000000
#define D_NODE  128
#define D_EDGE  64
#define HDIM    256
#define NGRAPH  512

#define MTILE 64
#define NODE_TILES (N_NODES / MTILE)   // 3125 (exact)
#define EDGE_TILES (N_EDGES / MTILE)   // 15625 (exact)
#define NCTA  128                      // output columns per CTA (HDIM split in 2)

// fused-kernel partition: 128 node CTAs + 316 edge CTAs = 444 = 3 x 148
#define FUSED_GRID   444
#define NODE_CTAS    128
#define EDGE_CTAS    316

// ---------------- scratch (device globals; no allocation) ----------------
__device__ float d_S_node[NGRAPH * HDIM];
__device__ float d_S_edge[NGRAPH * HDIM];
__device__ int   d_cnt_node[NGRAPH];
__device__ int   d_cnt_edge[NGRAPH];
__device__ unsigned short d_eb[N_EDGES];     // graph id per edge
__device__ int   d_esorted[N_EDGES];         // edge ids sorted by graph
__device__ int   d_cursor[NGRAPH];
__device__ __nv_bfloat16 d_Wt_node[HDIM * D_NODE];  // [n][k]  (transposed, bf16)
__device__ __nv_bfloat16 d_Wt_edge[HDIM * D_EDGE];  // [n][k]

// ---------------- asm helpers ----------------
#define LDSM_X4(r0, r1, r2, r3, addr)                                          \
    asm volatile("ldmatrix.sync.aligned.m8n8.x4.shared.b16 {%0,%1,%2,%3}, [%4];" \
                 : "=r"(r0), "=r"(r1), "=r"(r2), "=r"(r3) : "r"(addr))

#define MMA16816(c0, c1, c2, c3, a0, a1, a2, a3, b0, b1)                       \
    asm volatile(                                                              \
        "mma.sync.aligned.m16n8k16.row.col.f32.bf16.bf16.f32 "                 \
        "{%0,%1,%2,%3}, {%4,%5,%6,%7}, {%8,%9}, {%0,%1,%2,%3};\n"              \
        : "+f"(c0), "+f"(c1), "+f"(c2), "+f"(c3)                               \
        : "r"(a0), "r"(a1), "r"(a2), "r"(a3), "r"(b0), "r"(b1))

// ---------------- launch #1: zero sums + weight transpose + histograms ----
// (count buffers pre-zeroed by cudaMemsetAsync — zeroing here would race)
__global__ void k_setup(const float* __restrict__ Wn1, const float* __restrict__ We1,
                        const int* __restrict__ batch_idx, const int* __restrict__ edge_src)
{
    const int b = blockIdx.x;
    const int tid = threadIdx.x;
    if (b < 64) {
        int i = b * 256 + tid;
        for (int j = i; j < HDIM * D_NODE; j += 64 * 256) {
            int n = j / D_NODE, k = j % D_NODE;
            d_Wt_node[j] = __float2bfloat16(Wn1[k * HDIM + n]);
        }
        for (int j = i; j < HDIM * D_EDGE; j += 64 * 256) {
            int n = j / D_EDGE, k = j % D_EDGE;
            d_Wt_edge[j] = __float2bfloat16(We1[k * HDIM + n]);
        }
    } else if (b < 128) {
        int i = (b - 64) * 256 + tid;
        for (int j = i; j < NGRAPH * HDIM; j += 64 * 256) { d_S_node[j] = 0.f; d_S_edge[j] = 0.f; }
    } else if (b < 328) {
        __shared__ int h[NGRAPH];
        for (int j = tid; j < NGRAPH; j += 256) h[j] = 0;
        __syncthreads();
        int i = (b - 128) * 256 + tid;
        for (int n = i; n < N_NODES; n += 200 * 256) atomicAdd(&h[batch_idx[n]], 1);
        __syncthreads();
        for (int j = tid; j < NGRAPH; j += 256)
            if (h[j]) atomicAdd(&d_cnt_node[j], h[j]);
    } else {
        __shared__ int h[NGRAPH];
        for (int j = tid; j < NGRAPH; j += 256) h[j] = 0;
        __syncthreads();
        int i = (b - 328) * 256 + tid;
        for (int e = i; e < N_EDGES; e += 512 * 256) {
            int g = batch_idx[edge_src[e]];
            d_eb[e] = (unsigned short)g;
            atomicAdd(&h[g], 1);
        }
        __syncthreads();
        for (int j = tid; j < NGRAPH; j += 256)
            if (h[j]) atomicAdd(&d_cnt_edge[j], h[j]);
    }
}

// ---------------- launch #2: exclusive prefix sum of edge counts ----------
__global__ void k_scan() {
    __shared__ int wsum[16];
    int tid = threadIdx.x;
    int lane = tid & 31, w = tid >> 5;
    int v = d_cnt_edge[tid];
    int s = v;
    #pragma unroll
    for (int o = 1; o < 32; o <<= 1) {
        int t = __shfl_up_sync(0xffffffffu, s, o);
        if (lane >= o) s += t;
    }
    if (lane == 31) wsum[w] = s;
    __syncthreads();
    if (tid == 0) {
        int run = 0;
        for (int i = 0; i < 16; i++) { int t = wsum[i]; wsum[i] = run; run += t; }
    }
    __syncthreads();
    d_cursor[tid] = s + wsum[w] - v;   // exclusive
}

// ---------------- launch #3: counting-sort scatter, block-local ------------
// Two-pass per block: smem histogram -> ONE global atomicAdd per (block,graph)
// (16K global atomics total, vs 1M on 512 hot addresses before), then scatter
// using fast spread-bank smem counters. Per-graph contiguity preserved.
#define SC_BLOCKS 32
#define SC_CHUNK  (N_EDGES / SC_BLOCKS)   // 31250
__global__ void __launch_bounds__(256)
k_scatter() {
    __shared__ int h[NGRAPH];
    __shared__ int base[NGRAPH];
    const int tid = threadIdx.x;
    const int e0 = blockIdx.x * SC_CHUNK;

    for (int j = tid; j < NGRAPH; j += 256) h[j] = 0;
    __syncthreads();
    for (int i = tid; i < SC_CHUNK; i += 256)
        atomicAdd(&h[(int)d_eb[e0 + i]], 1);
    __syncthreads();
    for (int j = tid; j < NGRAPH; j += 256) {
        int c = h[j];
        base[j] = (c > 0) ? atomicAdd(&d_cursor[j], c) : 0;
        h[j] = 0;
    }
    __syncthreads();
    for (int i = tid; i < SC_CHUNK; i += 256) {
        int e = e0 + i;
        int g = (int)d_eb[e];
        int p = base[g] + atomicAdd(&h[g], 1);
        d_esorted[p] = e;
    }
}

// ================= launch #4: FUSED node+edge GEMM (profiled) ==============
// bid < 128  -> node phase (K=128), grid-stride 128 over 6250 units
// bid >= 128 -> edge phase (K=64, pipelined), grid-stride 316 over 31250 units
// All 444 CTAs co-resident (3/SM): heterogeneous warps fill each other's stalls.

// ---- edge phase (R10 structure: double-buffered As, 1 barrier/tile) ----
#define EKPAD 72
#define E_AS_OFF 18432                       // Ws = 128*72*2
#define E_ASB    9216                        // one As buffer = 64*72*2
#define E_GID    36864                       // 2 x 64 ints
#define E_ES     37376                       // 2 x 64 ints
#define E_BIAS   37888                       // 128 floats
#define E_SMEM   38400

__device__ __forceinline__ void edge_phase(
    const float* __restrict__ edge_attr, const float* __restrict__ be1,
    char* smem, uint32_t sbase, int vbid, int nctas)
{
    __nv_bfloat16* Ws = (__nv_bfloat16*)smem;
    __nv_bfloat16* As = (__nv_bfloat16*)(smem + E_AS_OFF);  // [2][64*72]
    int*   gid_s  = (int*)(smem + E_GID);                   // [2][64]
    int*   es_s   = (int*)(smem + E_ES);                    // [2][64]
    float* bias_s = (float*)(smem + E_BIAS);

    const int tid = threadIdx.x;
    const int nbase = (vbid & 1) * NCTA;     // stride even -> fixed per CTA

    const uint32_t* Wg32 = (const uint32_t*)d_Wt_edge;
    for (int j = tid; j < NCTA * 32; j += 256) {
        int n = j >> 5, k2 = j & 31;
        *(uint32_t*)&Ws[n * EKPAD + 2 * k2] = Wg32[(nbase + n) * 32 + k2];
    }
    if (tid < NCTA) bias_s[tid] = be1[nbase + tid];

    const int lane = tid & 31, warp = tid >> 5;
    const int wm = (warp & 1) * 32;
    const int wn = (warp >> 1) * 32;
    const int gID = lane >> 2, tig = lane & 3;

    const uint32_t a_off = (uint32_t)(((wm + (lane & 15)) * EKPAD + ((lane >> 4) << 3)) * 2);
    const int brow = (lane & 7) + ((lane >> 4) << 3);
    const int bkof = ((lane >> 3) & 1) << 3;
    const uint32_t b_addr0 = sbase + (uint32_t)(((wn + brow) * EKPAD + bkof) * 2);

    const int grow = tid >> 4;
    const int gq   = tid & 15;

    const int NB = 2 * EDGE_TILES;     // 31250

    // ---- prologue: stage first tile into buffer 0 ----
    {
        int r0 = (vbid >> 1) * MTILE;
        if (tid < MTILE) {
            int e = d_esorted[r0 + tid];
            es_s[tid]  = e;
            gid_s[tid] = (int)d_eb[e];
        }
    }
    __syncthreads();
    int gr0c[2], gr1c[2];
    gr0c[0] = gid_s[wm + gID];       gr0c[1] = gid_s[wm + 16 + gID];
    gr1c[0] = gid_s[wm + gID + 8];   gr1c[1] = gid_s[wm + 16 + gID + 8];
    int glo_c = gid_s[0], ghi_c = gid_s[MTILE - 1];
    {
        float4 v[4];
        #pragma unroll
        for (int i = 0; i < 4; i++)
            v[i] = *(const float4*)(edge_attr + (size_t)es_s[grow + 16 * i] * 64 + gq * 4);
        #pragma unroll
        for (int i = 0; i < 4; i++) {
            __nv_bfloat162 p0 = __float22bfloat162_rn(make_float2(v[i].x, v[i].y));
            __nv_bfloat162 p1 = __float22bfloat162_rn(make_float2(v[i].z, v[i].w));
            uint2 pk; pk.x = *(uint32_t*)&p0; pk.y = *(uint32_t*)&p1;
            *(uint2*)&As[(grow + 16 * i) * EKPAD + gq * 4] = pk;
        }
    }

    int p = 0;
    for (int b = vbid; b < NB; b += nctas) {
        const int q = p ^ 1;
        const int bn = b + nctas;
        const bool has_next = (bn < NB);

        if (has_next && tid < MTILE) {
            int r0n = (bn >> 1) * MTILE;
            int e = d_esorted[r0n + tid];
            es_s[q * MTILE + tid]  = e;
            gid_s[q * MTILE + tid] = (int)d_eb[e];
        }
        __syncthreads();   // As[p] STS + es/gid[q] visible; reads of As[q] done

        int gr0n[2] = {0, 0}, gr1n[2] = {0, 0}, glo_n = 0, ghi_n = -1;
        if (has_next) {
            gr0n[0] = gid_s[q * MTILE + wm + gID];
            gr0n[1] = gid_s[q * MTILE + wm + 16 + gID];
            gr1n[0] = gid_s[q * MTILE + wm + gID + 8];
            gr1n[1] = gid_s[q * MTILE + wm + 16 + gID + 8];
            glo_n = gid_s[q * MTILE];
            ghi_n = gid_s[q * MTILE + MTILE - 1];
        }

        float4 v[4];
        if (has_next) {
            #pragma unroll
            for (int i = 0; i < 4; i++)
                v[i] = *(const float4*)(edge_attr +
                        (size_t)es_s[q * MTILE + grow + 16 * i] * 64 + gq * 4);
        }

        const uint32_t a_base = sbase + E_AS_OFF + (uint32_t)(p * E_ASB) + a_off;
        float c[2][4][4];
        #pragma unroll
        for (int mf = 0; mf < 2; mf++)
            #pragma unroll
            for (int nf = 0; nf < 4; nf++)
                #pragma unroll
                for (int r = 0; r < 4; r++) c[mf][nf][r] = 0.f;

        #pragma unroll
        for (int ks = 0; ks < 4; ks++) {
            const uint32_t koff = (uint32_t)(ks * 32);
            uint32_t a[2][4];
            LDSM_X4(a[0][0], a[0][1], a[0][2], a[0][3], a_base + koff);
            LDSM_X4(a[1][0], a[1][1], a[1][2], a[1][3], a_base + 16 * EKPAD * 2 + koff);
            #pragma unroll
            for (int nfp = 0; nfp < 2; nfp++) {
                uint32_t b0, b1, b2, b3;
                LDSM_X4(b0, b1, b2, b3,
                        b_addr0 + (uint32_t)(nfp * 16 * EKPAD * 2) + koff);
                const int nf = 2 * nfp;
                MMA16816(c[0][nf][0], c[0][nf][1], c[0][nf][2], c[0][nf][3],
                         a[0][0], a[0][1], a[0][2], a[0][3], b0, b1);
                MMA16816(c[1][nf][0], c[1][nf][1], c[1][nf][2], c[1][nf][3],
                         a[1][0], a[1][1], a[1][2], a[1][3], b0, b1);
                MMA16816(c[0][nf+1][0], c[0][nf+1][1], c[0][nf+1][2], c[0][nf+1][3],
                         a[0][0], a[0][1], a[0][2], a[0][3], b2, b3);
                MMA16816(c[1][nf+1][0], c[1][nf+1][1], c[1][nf+1][2], c[1][nf+1][3],
                         a[1][0], a[1][1], a[1][2], a[1][3], b2, b3);
            }
        }

        #pragma unroll
        for (int nf = 0; nf < 4; nf++) {
            float b0 = bias_s[wn + nf * 8 + 2 * tig];
            float b1 = bias_s[wn + nf * 8 + 2 * tig + 1];
            #pragma unroll
            for (int mf = 0; mf < 2; mf++) {
                c[mf][nf][0] = fmaxf(c[mf][nf][0] + b0, 0.f);
                c[mf][nf][1] = fmaxf(c[mf][nf][1] + b1, 0.f);
                c[mf][nf][2] = fmaxf(c[mf][nf][2] + b0, 0.f);
                c[mf][nf][3] = fmaxf(c[mf][nf][3] + b1, 0.f);
            }
        }

        for (int g = glo_c; g <= ghi_c; ++g) {
            #pragma unroll
            for (int nf = 0; nf < 4; nf++) {
                float s0 = 0.f, s1 = 0.f;
                #pragma unroll
                for (int mf = 0; mf < 2; mf++) {
                    if (gr0c[mf] == g) { s0 += c[mf][nf][0]; s1 += c[mf][nf][1]; }
                    if (gr1c[mf] == g) { s0 += c[mf][nf][2]; s1 += c[mf][nf][3]; }
                }
                #pragma unroll
                for (int o = 4; o <= 16; o <<= 1) {
                    s0 += __shfl_xor_sync(0xffffffffu, s0, o);
                    s1 += __shfl_xor_sync(0xffffffffu, s1, o);
                }
                if (lane < 4) {
                    float* dst = &d_S_edge[g * HDIM + nbase + wn + nf * 8 + 2 * lane];
                    atomicAdd(dst,     s0);
                    atomicAdd(dst + 1, s1);
                }
            }
        }

        if (has_next) {
            #pragma unroll
            for (int i = 0; i < 4; i++) {
                __nv_bfloat162 p0 = __float22bfloat162_rn(make_float2(v[i].x, v[i].y));
                __nv_bfloat162 p1 = __float22bfloat162_rn(make_float2(v[i].z, v[i].w));
                uint2 pk; pk.x = *(uint32_t*)&p0; pk.y = *(uint32_t*)&p1;
                *(uint2*)&As[q * (E_ASB / 2) + (grow + 16 * i) * EKPAD + gq * 4] = pk;
            }
        }

        gr0c[0] = gr0n[0]; gr0c[1] = gr0n[1];
        gr1c[0] = gr1n[0]; gr1c[1] = gr1n[1];
        glo_c = glo_n; ghi_c = ghi_n;
        p = q;
    }
}

// ---- node phase (R7 structure, K=128) ----
#define NKPAD (D_NODE + 8)
#define N_WS_BYTES (NCTA * NKPAD * 2)            // 34816
#define N_AS_BYTES (MTILE * NKPAD * 2)           // 17408
#define SMEM_FUSED (N_WS_BYTES + N_AS_BYTES + 1024)   // 53248

__device__ __forceinline__ void node_phase(
    const float* __restrict__ x, const int* __restrict__ batch_idx,
    const float* __restrict__ bn1, char* smem, uint32_t sbase, int vbid, int nctas)
{
    __nv_bfloat16* Ws = (__nv_bfloat16*)(smem);
    __nv_bfloat16* As = (__nv_bfloat16*)(smem + N_WS_BYTES);
    int*   gid_s  = (int*)(smem + N_WS_BYTES + N_AS_BYTES);
    float* bias_s = (float*)(smem + N_WS_BYTES + N_AS_BYTES + 512);

    const int tid = threadIdx.x;
    const int nbase = (vbid & 1) * NCTA;

    const uint32_t* Wg32 = (const uint32_t*)d_Wt_node;
    for (int j = tid; j < NCTA * 64; j += 256) {
        int n = j >> 6, k2 = j & 63;
        *(uint32_t*)&Ws[n * NKPAD + 2 * k2] = Wg32[(nbase + n) * 64 + k2];
    }
    if (tid < NCTA) bias_s[tid] = bn1[nbase + tid];
    __syncthreads();

    const int lane = tid & 31, warp = tid >> 5;
    const int wm = (warp & 1) * 32;
    const int wn = (warp >> 1) * 32;
    const int gID = lane >> 2, tig = lane & 3;

    const uint32_t a_addr0 = sbase + N_WS_BYTES +
        (uint32_t)(((wm + (lane & 15)) * NKPAD + ((lane >> 4) << 3)) * 2);
    const uint32_t a_addr1 = a_addr0 + (uint32_t)(16 * NKPAD * 2);
    const int brow = (lane & 7) + ((lane >> 4) << 3);
    const int bkof = ((lane >> 3) & 1) << 3;
    const uint32_t b_addr0 = sbase + (uint32_t)(((wn + brow) * NKPAD + bkof) * 2);

    for (int b = vbid; b < 2 * NODE_TILES; b += nctas) {
        const int t = b >> 1;
        const int r0 = t * MTILE;

        __syncthreads();
        if (tid < MTILE) gid_s[tid] = batch_idx[r0 + tid];
        __syncthreads();

        #pragma unroll
        for (int base = 0; base < 8; base += 4) {
            float4 v[4];
            #pragma unroll
            for (int i = 0; i < 4; i++) {
                int j = tid + (base + i) * 256;
                int r = j >> 5, q = j & 31;
                v[i] = *(const float4*)(x + (size_t)(r0 + r) * D_NODE + q * 4);
            }
            #pragma unroll
            for (int i = 0; i < 4; i++) {
                int j = tid + (base + i) * 256;
                int r = j >> 5, q = j & 31;
                __nv_bfloat162 p0 = __float22bfloat162_rn(make_float2(v[i].x, v[i].y));
                __nv_bfloat162 p1 = __float22bfloat162_rn(make_float2(v[i].z, v[i].w));
                *(__nv_bfloat162*)&As[r * NKPAD + q * 4]     = p0;
                *(__nv_bfloat162*)&As[r * NKPAD + q * 4 + 2] = p1;
            }
        }
        __syncthreads();

        int gr0[2], gr1[2];
        #pragma unroll
        for (int mf = 0; mf < 2; mf++) {
            gr0[mf] = gid_s[wm + mf * 16 + gID];
            gr1[mf] = gid_s[wm + mf * 16 + gID + 8];
        }
        const int g_lo = gid_s[0];
        const int g_hi = gid_s[MTILE - 1];

        float c[2][4][4];
        #pragma unroll
        for (int mf = 0; mf < 2; mf++)
            #pragma unroll
            for (int nf = 0; nf < 4; nf++)
                #pragma unroll
                for (int r = 0; r < 4; r++) c[mf][nf][r] = 0.f;

        #pragma unroll
        for (int ks = 0; ks < 8; ks++) {
            const uint32_t koff = (uint32_t)(ks * 32);
            uint32_t a[2][4];
            LDSM_X4(a[0][0], a[0][1], a[0][2], a[0][3], a_addr0 + koff);
            LDSM_X4(a[1][0], a[1][1], a[1][2], a[1][3], a_addr1 + koff);
            #pragma unroll
            for (int nfp = 0; nfp < 2; nfp++) {
                uint32_t b0, b1, b2, b3;
                LDSM_X4(b0, b1, b2, b3,
                        b_addr0 + (uint32_t)(nfp * 16 * NKPAD * 2) + koff);
                const int nf = 2 * nfp;
                MMA16816(c[0][nf][0], c[0][nf][1], c[0][nf][2], c[0][nf][3],
                         a[0][0], a[0][1], a[0][2], a[0][3], b0, b1);
                MMA16816(c[1][nf][0], c[1][nf][1], c[1][nf][2], c[1][nf][3],
                         a[1][0], a[1][1], a[1][2], a[1][3], b0, b1);
                MMA16816(c[0][nf+1][0], c[0][nf+1][1], c[0][nf+1][2], c[0][nf+1][3],
                         a[0][0], a[0][1], a[0][2], a[0][3], b2, b3);
                MMA16816(c[1][nf+1][0], c[1][nf+1][1], c[1][nf+1][2], c[1][nf+1][3],
                         a[1][0], a[1][1], a[1][2], a[1][3], b2, b3);
            }
        }

        #pragma unroll
        for (int nf = 0; nf < 4; nf++) {
            float b0 = bias_s[wn + nf * 8 + 2 * tig];
            float b1 = bias_s[wn + nf * 8 + 2 * tig + 1];
            #pragma unroll
            for (int mf = 0; mf < 2; mf++) {
                c[mf][nf][0] = fmaxf(c[mf][nf][0] + b0, 0.f);
                c[mf][nf][1] = fmaxf(c[mf][nf][1] + b1, 0.f);
                c[mf][nf][2] = fmaxf(c[mf][nf][2] + b0, 0.f);
                c[mf][nf][3] = fmaxf(c[mf][nf][3] + b1, 0.f);
            }
        }

        for (int g = g_lo; g <= g_hi; ++g) {
            #pragma unroll
            for (int nf = 0; nf < 4; nf++) {
                float s0 = 0.f, s1 = 0.f;
                #pragma unroll
                for (int mf = 0; mf < 2; mf++) {
                    if (gr0[mf] == g) { s0 += c[mf][nf][0]; s1 += c[mf][nf][1]; }
                    if (gr1[mf] == g) { s0 += c[mf][nf][2]; s1 += c[mf][nf][3]; }
                }
                #pragma unroll
                for (int o = 4; o <= 16; o <<= 1) {
                    s0 += __shfl_xor_sync(0xffffffffu, s0, o);
                    s1 += __shfl_xor_sync(0xffffffffu, s1, o);
                }
                if (lane < 4) {
                    float* dst = &d_S_node[g * HDIM + nbase + wn + nf * 8 + 2 * lane];
                    atomicAdd(dst,     s0);
                    atomicAdd(dst + 1, s1);
                }
            }
        }
    }
}

__global__ void __launch_bounds__(256, 3)
k_gemm_fused(const float* __restrict__ edge_attr, const float* __restrict__ be1,
             const float* __restrict__ x, const int* __restrict__ batch_idx,
             const float* __restrict__ bn1)
{
    extern __shared__ char smem[];
    uint32_t sbase = (uint32_t)__cvta_generic_to_shared(smem);
    const int bid = blockIdx.x;
    if (bid < NODE_CTAS) {
        node_phase(x, batch_idx, bn1, smem, sbase, bid, NODE_CTAS);
    } else {
        edge_phase(edge_attr, be1, smem, sbase, bid - NODE_CTAS, EDGE_CTAS);
    }
}

// ---------------- launch #5: means -> layer-2 -> combine ------------------
__global__ void __launch_bounds__(256)
k_finalize(const float* __restrict__ Wn2, const float* __restrict__ bn2,
           const float* __restrict__ We2, const float* __restrict__ be2,
           const float* __restrict__ Wc,  const float* __restrict__ bc,
           float* __restrict__ out)
{
    __shared__ float mn[8][HDIM], me[8][HDIM], gr[8][HDIM];
    __shared__ int fn[8], fe[8];
    const int tid = threadIdx.x;
    const int gbase = blockIdx.x * 8;

    #pragma unroll
    for (int gg = 0; gg < 8; gg++) {
        int g = gbase + gg;
        int cn = d_cnt_node[g], ce = d_cnt_edge[g];
        if (tid == 0) { fn[gg] = cn; fe[gg] = ce; }
        mn[gg][tid] = (cn > 0) ? d_S_node[g * HDIM + tid] / (float)cn : 0.f;
        me[gg][tid] = (ce > 0) ? d_S_edge[g * HDIM + tid] / (float)ce : 0.f;
    }
    __syncthreads();

    float an[8], ae[8];
    #pragma unroll
    for (int gg = 0; gg < 8; gg++) { an[gg] = 0.f; ae[gg] = 0.f; }
    for (int j = 0; j < HDIM; j++) {
        float w1 = Wn2[j * HDIM + tid];
        float w2 = We2[j * HDIM + tid];
        #pragma unroll
        for (int gg = 0; gg < 8; gg++) {
            an[gg] += mn[gg][j] * w1;
            ae[gg] += me[gg][j] * w2;
        }
    }
    float b2n = bn2[tid], b2e = be2[tid];
    #pragma unroll
    for (int gg = 0; gg < 8; gg++) {
        float nr = (fn[gg] > 0) ? an[gg] + b2n : 0.f;
        float er = (fe[gg] > 0) ? ae[gg] + b2e : 0.f;
        gr[gg][tid] = nr + er;
    }
    __syncthreads();

    float ao[8];
    #pragma unroll
    for (int gg = 0; gg < 8; gg++) ao[gg] = 0.f;
    for (int j = 0; j < HDIM; j++) {
        float w = Wc[j * HDIM + tid];
        #pragma unroll
        for (int gg = 0; gg < 8; gg++) ao[gg] += gr[gg][j] * w;
    }
    float bcv = bc[tid];
    #pragma unroll
    for (int gg = 0; gg < 8; gg++)
        out[(gbase + gg) * HDIM + tid] = ao[gg] + bcv;
}

// ---------------- launch ----------------
extern "C" void kernel_launch(void* const* d_in, const int* in_sizes, int n_in,
                              void* d_out, int out_size)
{
    const float* x         = (const float*)d_in[0];
    const float* edge_attr = (const float*)d_in[1];
    const int*   batch_idx = (const int*)d_in[2];
    const int*   edge_src  = (const int*)d_in[3];
    const float* Wn1 = (const float*)d_in[4];
    const float* bn1 = (const float*)d_in[5];
    const float* Wn2 = (const float*)d_in[6];
    const float* bn2 = (const float*)d_in[7];
    const float* We1 = (const float*)d_in[8];
    const float* be1 = (const float*)d_in[9];
    const float* We2 = (const float*)d_in[10];
    const float* be2 = (const float*)d_in[11];
    const float* Wc  = (const float*)d_in[12];
    const float* bc  = (const float*)d_in[13];
    float* out = (float*)d_out;

    (void)in_sizes; (void)n_in; (void)out_size;

    cudaFuncSetAttribute(k_gemm_fused, cudaFuncAttributeMaxDynamicSharedMemorySize, SMEM_FUSED);

    // zero the histogram counters before k_setup's atomics
    void* p_cn = nullptr; void* p_ce = nullptr;
    cudaGetSymbolAddress(&p_cn, d_cnt_node);
    cudaGetSymbolAddress(&p_ce, d_cnt_edge);
    cudaMemsetAsync(p_cn, 0, NGRAPH * sizeof(int));
    cudaMemsetAsync(p_ce, 0, NGRAPH * sizeof(int));

    k_setup<<<840, 256>>>(Wn1, We1, batch_idx, edge_src);                    // kernel #1
    k_scan<<<1, 512>>>();                                                    // #2
    k_scatter<<<SC_BLOCKS, 256>>>();                                         // #3
    k_gemm_fused<<<FUSED_GRID, 256, SMEM_FUSED>>>(edge_attr, be1,
                                                  x, batch_idx, bn1);        // #4 (profiled)
    k_finalize<<<64, 256>>>(Wn2, bn2, We2, be2, Wc, bc, out);                // #5
}

// round 15
// speedup vs baseline: 1.2794x; 1.0888x over previous
#include <cuda_runtime.h>
#include <cuda_bf16.h>
#include <cstdint>

// ---------------- problem constants (fixed shapes) ----------------
#define N_NODES 200000
#define N_EDGES 1000000
#define D_NODE  128
#define D_EDGE  64
#define HDIM    256
#define NGRAPH  512

#define MTILE 64
#define NODE_TILES (N_NODES / MTILE)   // 3125 (exact)
#define EDGE_TILES (N_EDGES / MTILE)   // 15625 (exact)
#define NCTA  128                      // output columns per CTA (HDIM split in 2)

// ---------------- scratch (device globals; no allocation) ----------------
__device__ float d_S_node[NGRAPH * HDIM];
__device__ float d_S_edge[NGRAPH * HDIM];
__device__ int   d_cnt_node[NGRAPH];
__device__ int   d_cnt_edge[NGRAPH];
__device__ unsigned short d_eb[N_EDGES];     // graph id per edge
__device__ int   d_esorted[N_EDGES];         // edge ids sorted by graph
__device__ int   d_cursor[NGRAPH];
__device__ __nv_bfloat16 d_Wt_node[HDIM * D_NODE];  // [n][k]  (transposed, bf16)
__device__ __nv_bfloat16 d_Wt_edge[HDIM * D_EDGE];  // [n][k]

// ---------------- asm helpers ----------------
#define LDSM_X4(r0, r1, r2, r3, addr)                                          \
    asm volatile("ldmatrix.sync.aligned.m8n8.x4.shared.b16 {%0,%1,%2,%3}, [%4];" \
                 : "=r"(r0), "=r"(r1), "=r"(r2), "=r"(r3) : "r"(addr))

#define MMA16816(c0, c1, c2, c3, a0, a1, a2, a3, b0, b1)                       \
    asm volatile(                                                              \
        "mma.sync.aligned.m16n8k16.row.col.f32.bf16.bf16.f32 "                 \
        "{%0,%1,%2,%3}, {%4,%5,%6,%7}, {%8,%9}, {%0,%1,%2,%3};\n"              \
        : "+f"(c0), "+f"(c1), "+f"(c2), "+f"(c3)                               \
        : "r"(a0), "r"(a1), "r"(a2), "r"(a3), "r"(b0), "r"(b1))

// ---------------- launch #1: weight transpose + edge gid/hist + node counts
// (cnt/S buffers pre-zeroed by cudaMemsetAsync; zeroing here would race)
__global__ void k_setup(const float* __restrict__ Wn1, const float* __restrict__ We1,
                        const int* __restrict__ batch_idx, const int* __restrict__ edge_src)
{
    const int b = blockIdx.x;
    const int tid = threadIdx.x;
    if (b < 512) {
        // edge graph-id + histogram
        __shared__ int h[NGRAPH];
        for (int j = tid; j < NGRAPH; j += 256) h[j] = 0;
        __syncthreads();
        int i = b * 256 + tid;
        for (int e = i; e < N_EDGES; e += 512 * 256) {
            int g = batch_idx[edge_src[e]];
            d_eb[e] = (unsigned short)g;
            atomicAdd(&h[g], 1);
        }
        __syncthreads();
        for (int j = tid; j < NGRAPH; j += 256)
            if (h[j]) atomicAdd(&d_cnt_edge[j], h[j]);
    } else if (b < 576) {
        // weight transpose + bf16 convert
        int i = (b - 512) * 256 + tid;
        for (int j = i; j < HDIM * D_NODE; j += 64 * 256) {
            int n = j / D_NODE, k = j % D_NODE;
            d_Wt_node[j] = __float2bfloat16(Wn1[k * HDIM + n]);
        }
        for (int j = i; j < HDIM * D_EDGE; j += 64 * 256) {
            int n = j / D_EDGE, k = j % D_EDGE;
            d_Wt_edge[j] = __float2bfloat16(We1[k * HDIM + n]);
        }
    } else {
        // node counts via binary search over sorted batch_idx.
        // ONE block of 256 threads covering ALL 512 graphs (R13 bug: the old
        // `if (tid < NGRAPH)` guard left graphs 256..511 unwritten).
        for (int g = tid; g < NGRAPH; g += 256) {
            int lo = 0, hi = N_NODES;
            while (lo < hi) { int m = (lo + hi) >> 1; if (batch_idx[m] < g) lo = m + 1; else hi = m; }
            int lb0 = lo;
            lo = 0; hi = N_NODES;
            int g1 = g + 1;
            while (lo < hi) { int m = (lo + hi) >> 1; if (batch_idx[m] < g1) lo = m + 1; else hi = m; }
            d_cnt_node[g] = lo - lb0;
        }
    }
}

// ---------------- launch #2: exclusive prefix sum of edge counts ----------
__global__ void k_scan() {
    __shared__ int wsum[16];
    int tid = threadIdx.x;
    int lane = tid & 31, w = tid >> 5;
    int v = d_cnt_edge[tid];
    int s = v;
    #pragma unroll
    for (int o = 1; o < 32; o <<= 1) {
        int t = __shfl_up_sync(0xffffffffu, s, o);
        if (lane >= o) s += t;
    }
    if (lane == 31) wsum[w] = s;
    __syncthreads();
    if (tid == 0) {
        int run = 0;
        for (int i = 0; i < 16; i++) { int t = wsum[i]; wsum[i] = run; run += t; }
    }
    __syncthreads();
    d_cursor[tid] = s + wsum[w] - v;   // exclusive
}

// ---------------- launch #3: counting-sort scatter, block-local ------------
#define SC_BLOCKS 32
#define SC_CHUNK  (N_EDGES / SC_BLOCKS)   // 31250
__global__ void __launch_bounds__(256)
k_scatter() {
    __shared__ int h[NGRAPH];
    __shared__ int base[NGRAPH];
    const int tid = threadIdx.x;
    const int e0 = blockIdx.x * SC_CHUNK;

    for (int j = tid; j < NGRAPH; j += 256) h[j] = 0;
    __syncthreads();
    for (int i = tid; i < SC_CHUNK; i += 256)
        atomicAdd(&h[(int)d_eb[e0 + i]], 1);
    __syncthreads();
    for (int j = tid; j < NGRAPH; j += 256) {
        int c = h[j];
        base[j] = (c > 0) ? atomicAdd(&d_cursor[j], c) : 0;
        h[j] = 0;
    }
    __syncthreads();
    for (int i = tid; i < SC_CHUNK; i += 256) {
        int e = e0 + i;
        int g = (int)d_eb[e];
        int p = base[g] + atomicAdd(&h[g], 1);
        d_esorted[p] = e;
    }
}

// ================= launch #4: EDGE GEMM (R10 config — best measured) =======
#define EKPAD 72
#define E_AS_OFF 18432                       // Ws = 128*72*2
#define E_ASB    9216                        // one As buffer = 64*72*2
#define E_GID    36864                       // 2 x 64 ints
#define E_ES     37376                       // 2 x 64 ints
#define E_BIAS   37888                       // 128 floats
#define E_SMEM   38400

__global__ void __launch_bounds__(256, 3)
k_gemm_edge(const float* __restrict__ edge_attr, const float* __restrict__ be1)
{
    extern __shared__ char smem[];
    uint32_t sbase = (uint32_t)__cvta_generic_to_shared(smem);
    __nv_bfloat16* Ws = (__nv_bfloat16*)smem;
    __nv_bfloat16* As = (__nv_bfloat16*)(smem + E_AS_OFF);  // [2][64*72]
    int*   gid_s  = (int*)(smem + E_GID);                   // [2][64]
    int*   es_s   = (int*)(smem + E_ES);                    // [2][64]
    float* bias_s = (float*)(smem + E_BIAS);

    const int tid = threadIdx.x;
    const int nbase = (blockIdx.x & 1) * NCTA;   // grid stride even -> fixed per CTA

    const uint32_t* Wg32 = (const uint32_t*)d_Wt_edge;
    for (int j = tid; j < NCTA * 32; j += 256) {
        int n = j >> 5, k2 = j & 31;
        *(uint32_t*)&Ws[n * EKPAD + 2 * k2] = Wg32[(nbase + n) * 32 + k2];
    }
    if (tid < NCTA) bias_s[tid] = be1[nbase + tid];

    const int lane = tid & 31, warp = tid >> 5;
    const int wm = (warp & 1) * 32;
    const int wn = (warp >> 1) * 32;
    const int gID = lane >> 2, tig = lane & 3;

    const uint32_t a_off = (uint32_t)(((wm + (lane & 15)) * EKPAD + ((lane >> 4) << 3)) * 2);
    const int brow = (lane & 7) + ((lane >> 4) << 3);
    const int bkof = ((lane >> 3) & 1) << 3;
    const uint32_t b_addr0 = sbase + (uint32_t)(((wn + brow) * EKPAD + bkof) * 2);

    const int grow = tid >> 4;
    const int gq   = tid & 15;

    const int NB = 2 * EDGE_TILES;     // 31250
    const int stride = gridDim.x;

    // ---- prologue: stage first tile into buffer 0 ----
    {
        int r0 = (blockIdx.x >> 1) * MTILE;
        if (tid < MTILE) {
            int e = d_esorted[r0 + tid];
            es_s[tid]  = e;
            gid_s[tid] = (int)d_eb[e];
        }
    }
    __syncthreads();   // Ws + bias + first indices visible
    int gr0c[2], gr1c[2];
    gr0c[0] = gid_s[wm + gID];       gr0c[1] = gid_s[wm + 16 + gID];
    gr1c[0] = gid_s[wm + gID + 8];   gr1c[1] = gid_s[wm + 16 + gID + 8];
    int glo_c = gid_s[0], ghi_c = gid_s[MTILE - 1];
    {
        float4 v[4];
        #pragma unroll
        for (int i = 0; i < 4; i++)
            v[i] = *(const float4*)(edge_attr + (size_t)es_s[grow + 16 * i] * 64 + gq * 4);
        #pragma unroll
        for (int i = 0; i < 4; i++) {
            __nv_bfloat162 p0 = __float22bfloat162_rn(make_float2(v[i].x, v[i].y));
            __nv_bfloat162 p1 = __float22bfloat162_rn(make_float2(v[i].z, v[i].w));
            uint2 pk; pk.x = *(uint32_t*)&p0; pk.y = *(uint32_t*)&p1;
            *(uint2*)&As[(grow + 16 * i) * EKPAD + gq * 4] = pk;
        }
    }

    int p = 0;
    for (int b = blockIdx.x; b < NB; b += stride) {
        const int q = p ^ 1;
        const int bn = b + stride;
        const bool has_next = (bn < NB);

        if (has_next && tid < MTILE) {
            int r0n = (bn >> 1) * MTILE;
            int e = d_esorted[r0n + tid];
            es_s[q * MTILE + tid]  = e;
            gid_s[q * MTILE + tid] = (int)d_eb[e];
        }
        __syncthreads();   // As[p] STS + es/gid[q] visible; all reads of As[q] done

        int gr0n[2] = {0, 0}, gr1n[2] = {0, 0}, glo_n = 0, ghi_n = -1;
        if (has_next) {
            gr0n[0] = gid_s[q * MTILE + wm + gID];
            gr0n[1] = gid_s[q * MTILE + wm + 16 + gID];
            gr1n[0] = gid_s[q * MTILE + wm + gID + 8];
            gr1n[1] = gid_s[q * MTILE + wm + 16 + gID + 8];
            glo_n = gid_s[q * MTILE];
            ghi_n = gid_s[q * MTILE + MTILE - 1];
        }

        float4 v[4];
        if (has_next) {
            #pragma unroll
            for (int i = 0; i < 4; i++)
                v[i] = *(const float4*)(edge_attr +
                        (size_t)es_s[q * MTILE + grow + 16 * i] * 64 + gq * 4);
        }

        const uint32_t a_base = sbase + E_AS_OFF + (uint32_t)(p * E_ASB) + a_off;
        float c[2][4][4];
        #pragma unroll
        for (int mf = 0; mf < 2; mf++)
            #pragma unroll
            for (int nf = 0; nf < 4; nf++)
                #pragma unroll
                for (int r = 0; r < 4; r++) c[mf][nf][r] = 0.f;

        #pragma unroll
        for (int ks = 0; ks < 4; ks++) {
            const uint32_t koff = (uint32_t)(ks * 32);
            uint32_t a[2][4];
            LDSM_X4(a[0][0], a[0][1], a[0][2], a[0][3], a_base + koff);
            LDSM_X4(a[1][0], a[1][1], a[1][2], a[1][3], a_base + 16 * EKPAD * 2 + koff);
            #pragma unroll
            for (int nfp = 0; nfp < 2; nfp++) {
                uint32_t b0, b1, b2, b3;
                LDSM_X4(b0, b1, b2, b3,
                        b_addr0 + (uint32_t)(nfp * 16 * EKPAD * 2) + koff);
                const int nf = 2 * nfp;
                MMA16816(c[0][nf][0], c[0][nf][1], c[0][nf][2], c[0][nf][3],
                         a[0][0], a[0][1], a[0][2], a[0][3], b0, b1);
                MMA16816(c[1][nf][0], c[1][nf][1], c[1][nf][2], c[1][nf][3],
                         a[1][0], a[1][1], a[1][2], a[1][3], b0, b1);
                MMA16816(c[0][nf+1][0], c[0][nf+1][1], c[0][nf+1][2], c[0][nf+1][3],
                         a[0][0], a[0][1], a[0][2], a[0][3], b2, b3);
                MMA16816(c[1][nf+1][0], c[1][nf+1][1], c[1][nf+1][2], c[1][nf+1][3],
                         a[1][0], a[1][1], a[1][2], a[1][3], b2, b3);
            }
        }

        #pragma unroll
        for (int nf = 0; nf < 4; nf++) {
            float b0 = bias_s[wn + nf * 8 + 2 * tig];
            float b1 = bias_s[wn + nf * 8 + 2 * tig + 1];
            #pragma unroll
            for (int mf = 0; mf < 2; mf++) {
                c[mf][nf][0] = fmaxf(c[mf][nf][0] + b0, 0.f);
                c[mf][nf][1] = fmaxf(c[mf][nf][1] + b1, 0.f);
                c[mf][nf][2] = fmaxf(c[mf][nf][2] + b0, 0.f);
                c[mf][nf][3] = fmaxf(c[mf][nf][3] + b1, 0.f);
            }
        }

        for (int g = glo_c; g <= ghi_c; ++g) {
            #pragma unroll
            for (int nf = 0; nf < 4; nf++) {
                float s0 = 0.f, s1 = 0.f;
                #pragma unroll
                for (int mf = 0; mf < 2; mf++) {
                    if (gr0c[mf] == g) { s0 += c[mf][nf][0]; s1 += c[mf][nf][1]; }
                    if (gr1c[mf] == g) { s0 += c[mf][nf][2]; s1 += c[mf][nf][3]; }
                }
                #pragma unroll
                for (int o = 4; o <= 16; o <<= 1) {
                    s0 += __shfl_xor_sync(0xffffffffu, s0, o);
                    s1 += __shfl_xor_sync(0xffffffffu, s1, o);
                }
                if (lane < 4) {
                    float* dst = &d_S_edge[g * HDIM + nbase + wn + nf * 8 + 2 * lane];
                    atomicAdd(dst,     s0);
                    atomicAdd(dst + 1, s1);
                }
            }
        }

        if (has_next) {
            #pragma unroll
            for (int i = 0; i < 4; i++) {
                __nv_bfloat162 p0 = __float22bfloat162_rn(make_float2(v[i].x, v[i].y));
                __nv_bfloat162 p1 = __float22bfloat162_rn(make_float2(v[i].z, v[i].w));
                uint2 pk; pk.x = *(uint32_t*)&p0; pk.y = *(uint32_t*)&p1;
                *(uint2*)&As[q * (E_ASB / 2) + (grow + 16 * i) * EKPAD + gq * 4] = pk;
            }
        }

        gr0c[0] = gr0n[0]; gr0c[1] = gr0n[1];
        gr1c[0] = gr1n[0]; gr1c[1] = gr1n[1];
        glo_c = glo_n; ghi_c = ghi_n;
        p = q;
    }
}

// ================= launch #5: NODE GEMM (R7 config, measured 70.9us) ======
#define NKPAD (D_NODE + 8)
#define N_WS_BYTES (NCTA * NKPAD * 2)            // 34816
#define N_AS_BYTES (MTILE * NKPAD * 2)           // 17408
#define SMEM_NODE (N_WS_BYTES + N_AS_BYTES + 1024)   // 53248

__global__ void __launch_bounds__(256, 4)
k_gemm_node(const float* __restrict__ x, const int* __restrict__ batch_idx,
            const float* __restrict__ bn1)
{
    extern __shared__ char smem[];
    uint32_t sbase = (uint32_t)__cvta_generic_to_shared(smem);
    __nv_bfloat16* Ws = (__nv_bfloat16*)(smem);
    __nv_bfloat16* As = (__nv_bfloat16*)(smem + N_WS_BYTES);
    int*   gid_s  = (int*)(smem + N_WS_BYTES + N_AS_BYTES);
    float* bias_s = (float*)(smem + N_WS_BYTES + N_AS_BYTES + 512);

    const int tid = threadIdx.x;
    const int nbase = (blockIdx.x & 1) * NCTA;

    const uint32_t* Wg32 = (const uint32_t*)d_Wt_node;
    for (int j = tid; j < NCTA * 64; j += 256) {
        int n = j >> 6, k2 = j & 63;
        *(uint32_t*)&Ws[n * NKPAD + 2 * k2] = Wg32[(nbase + n) * 64 + k2];
    }
    if (tid < NCTA) bias_s[tid] = bn1[nbase + tid];
    __syncthreads();

    const int lane = tid & 31, warp = tid >> 5;
    const int wm = (warp & 1) * 32;
    const int wn = (warp >> 1) * 32;
    const int gID = lane >> 2, tig = lane & 3;

    const uint32_t a_addr0 = sbase + N_WS_BYTES +
        (uint32_t)(((wm + (lane & 15)) * NKPAD + ((lane >> 4) << 3)) * 2);
    const uint32_t a_addr1 = a_addr0 + (uint32_t)(16 * NKPAD * 2);
    const int brow = (lane & 7) + ((lane >> 4) << 3);
    const int bkof = ((lane >> 3) & 1) << 3;
    const uint32_t b_addr0 = sbase + (uint32_t)(((wn + brow) * NKPAD + bkof) * 2);

    for (int b = blockIdx.x; b < 2 * NODE_TILES; b += gridDim.x) {
        const int t = b >> 1;
        const int r0 = t * MTILE;

        __syncthreads();
        if (tid < MTILE) gid_s[tid] = batch_idx[r0 + tid];
        __syncthreads();

        #pragma unroll
        for (int base = 0; base < 8; base += 4) {
            float4 v[4];
            #pragma unroll
            for (int i = 0; i < 4; i++) {
                int j = tid + (base + i) * 256;
                int r = j >> 5, q = j & 31;
                v[i] = *(const float4*)(x + (size_t)(r0 + r) * D_NODE + q * 4);
            }
            #pragma unroll
            for (int i = 0; i < 4; i++) {
                int j = tid + (base + i) * 256;
                int r = j >> 5, q = j & 31;
                __nv_bfloat162 p0 = __float22bfloat162_rn(make_float2(v[i].x, v[i].y));
                __nv_bfloat162 p1 = __float22bfloat162_rn(make_float2(v[i].z, v[i].w));
                *(__nv_bfloat162*)&As[r * NKPAD + q * 4]     = p0;
                *(__nv_bfloat162*)&As[r * NKPAD + q * 4 + 2] = p1;
            }
        }
        __syncthreads();

        int gr0[2], gr1[2];
        #pragma unroll
        for (int mf = 0; mf < 2; mf++) {
            gr0[mf] = gid_s[wm + mf * 16 + gID];
            gr1[mf] = gid_s[wm + mf * 16 + gID + 8];
        }
        const int g_lo = gid_s[0];
        const int g_hi = gid_s[MTILE - 1];

        float c[2][4][4];
        #pragma unroll
        for (int mf = 0; mf < 2; mf++)
            #pragma unroll
            for (int nf = 0; nf < 4; nf++)
                #pragma unroll
                for (int r = 0; r < 4; r++) c[mf][nf][r] = 0.f;

        #pragma unroll
        for (int ks = 0; ks < 8; ks++) {
            const uint32_t koff = (uint32_t)(ks * 32);
            uint32_t a[2][4];
            LDSM_X4(a[0][0], a[0][1], a[0][2], a[0][3], a_addr0 + koff);
            LDSM_X4(a[1][0], a[1][1], a[1][2], a[1][3], a_addr1 + koff);
            #pragma unroll
            for (int nfp = 0; nfp < 2; nfp++) {
                uint32_t b0, b1, b2, b3;
                LDSM_X4(b0, b1, b2, b3,
                        b_addr0 + (uint32_t)(nfp * 16 * NKPAD * 2) + koff);
                const int nf = 2 * nfp;
                MMA16816(c[0][nf][0], c[0][nf][1], c[0][nf][2], c[0][nf][3],
                         a[0][0], a[0][1], a[0][2], a[0][3], b0, b1);
                MMA16816(c[1][nf][0], c[1][nf][1], c[1][nf][2], c[1][nf][3],
                         a[1][0], a[1][1], a[1][2], a[1][3], b0, b1);
                MMA16816(c[0][nf+1][0], c[0][nf+1][1], c[0][nf+1][2], c[0][nf+1][3],
                         a[0][0], a[0][1], a[0][2], a[0][3], b2, b3);
                MMA16816(c[1][nf+1][0], c[1][nf+1][1], c[1][nf+1][2], c[1][nf+1][3],
                         a[1][0], a[1][1], a[1][2], a[1][3], b2, b3);
            }
        }

        #pragma unroll
        for (int nf = 0; nf < 4; nf++) {
            float b0 = bias_s[wn + nf * 8 + 2 * tig];
            float b1 = bias_s[wn + nf * 8 + 2 * tig + 1];
            #pragma unroll
            for (int mf = 0; mf < 2; mf++) {
                c[mf][nf][0] = fmaxf(c[mf][nf][0] + b0, 0.f);
                c[mf][nf][1] = fmaxf(c[mf][nf][1] + b1, 0.f);
                c[mf][nf][2] = fmaxf(c[mf][nf][2] + b0, 0.f);
                c[mf][nf][3] = fmaxf(c[mf][nf][3] + b1, 0.f);
            }
        }

        for (int g = g_lo; g <= g_hi; ++g) {
            #pragma unroll
            for (int nf = 0; nf < 4; nf++) {
                float s0 = 0.f, s1 = 0.f;
                #pragma unroll
                for (int mf = 0; mf < 2; mf++) {
                    if (gr0[mf] == g) { s0 += c[mf][nf][0]; s1 += c[mf][nf][1]; }
                    if (gr1[mf] == g) { s0 += c[mf][nf][2]; s1 += c[mf][nf][3]; }
                }
                #pragma unroll
                for (int o = 4; o <= 16; o <<= 1) {
                    s0 += __shfl_xor_sync(0xffffffffu, s0, o);
                    s1 += __shfl_xor_sync(0xffffffffu, s1, o);
                }
                if (lane < 4) {
                    float* dst = &d_S_node[g * HDIM + nbase + wn + nf * 8 + 2 * lane];
                    atomicAdd(dst,     s0);
                    atomicAdd(dst + 1, s1);
                }
            }
        }
    }
}

// ---------------- launch #6: means -> layer-2 -> combine ------------------
__global__ void __launch_bounds__(256)
k_finalize(const float* __restrict__ Wn2, const float* __restrict__ bn2,
           const float* __restrict__ We2, const float* __restrict__ be2,
           const float* __restrict__ Wc,  const float* __restrict__ bc,
           float* __restrict__ out)
{
    __shared__ float mn[8][HDIM], me[8][HDIM], gr[8][HDIM];
    __shared__ int fn[8], fe[8];
    const int tid = threadIdx.x;
    const int gbase = blockIdx.x * 8;

    #pragma unroll
    for (int gg = 0; gg < 8; gg++) {
        int g = gbase + gg;
        int cn = d_cnt_node[g], ce = d_cnt_edge[g];
        if (tid == 0) { fn[gg] = cn; fe[gg] = ce; }
        mn[gg][tid] = (cn > 0) ? d_S_node[g * HDIM + tid] / (float)cn : 0.f;
        me[gg][tid] = (ce > 0) ? d_S_edge[g * HDIM + tid] / (float)ce : 0.f;
    }
    __syncthreads();

    float an[8], ae[8];
    #pragma unroll
    for (int gg = 0; gg < 8; gg++) { an[gg] = 0.f; ae[gg] = 0.f; }
    for (int j = 0; j < HDIM; j++) {
        float w1 = Wn2[j * HDIM + tid];
        float w2 = We2[j * HDIM + tid];
        #pragma unroll
        for (int gg = 0; gg < 8; gg++) {
            an[gg] += mn[gg][j] * w1;
            ae[gg] += me[gg][j] * w2;
        }
    }
    float b2n = bn2[tid], b2e = be2[tid];
    #pragma unroll
    for (int gg = 0; gg < 8; gg++) {
        float nr = (fn[gg] > 0) ? an[gg] + b2n : 0.f;
        float er = (fe[gg] > 0) ? ae[gg] + b2e : 0.f;
        gr[gg][tid] = nr + er;
    }
    __syncthreads();

    float ao[8];
    #pragma unroll
    for (int gg = 0; gg < 8; gg++) ao[gg] = 0.f;
    for (int j = 0; j < HDIM; j++) {
        float w = Wc[j * HDIM + tid];
        #pragma unroll
        for (int gg = 0; gg < 8; gg++) ao[gg] += gr[gg][j] * w;
    }
    float bcv = bc[tid];
    #pragma unroll
    for (int gg = 0; gg < 8; gg++)
        out[(gbase + gg) * HDIM + tid] = ao[gg] + bcv;
}

// ---------------- launch ----------------
extern "C" void kernel_launch(void* const* d_in, const int* in_sizes, int n_in,
                              void* d_out, int out_size)
{
    const float* x         = (const float*)d_in[0];
    const float* edge_attr = (const float*)d_in[1];
    const int*   batch_idx = (const int*)d_in[2];
    const int*   edge_src  = (const int*)d_in[3];
    const float* Wn1 = (const float*)d_in[4];
    const float* bn1 = (const float*)d_in[5];
    const float* Wn2 = (const float*)d_in[6];
    const float* bn2 = (const float*)d_in[7];
    const float* We1 = (const float*)d_in[8];
    const float* be1 = (const float*)d_in[9];
    const float* We2 = (const float*)d_in[10];
    const float* be2 = (const float*)d_in[11];
    const float* Wc  = (const float*)d_in[12];
    const float* bc  = (const float*)d_in[13];
    float* out = (float*)d_out;

    (void)in_sizes; (void)n_in; (void)out_size;

    cudaFuncSetAttribute(k_gemm_edge, cudaFuncAttributeMaxDynamicSharedMemorySize, E_SMEM);
    cudaFuncSetAttribute(k_gemm_node, cudaFuncAttributeMaxDynamicSharedMemorySize, SMEM_NODE);

    // zero scratch via memset nodes (not kernel launches)
    void* p;
    cudaGetSymbolAddress(&p, d_cnt_edge);  cudaMemsetAsync(p, 0, NGRAPH * sizeof(int));
    cudaGetSymbolAddress(&p, d_cnt_node);  cudaMemsetAsync(p, 0, NGRAPH * sizeof(int));
    cudaGetSymbolAddress(&p, d_S_node);    cudaMemsetAsync(p, 0, NGRAPH * HDIM * sizeof(float));
    cudaGetSymbolAddress(&p, d_S_edge);    cudaMemsetAsync(p, 0, NGRAPH * HDIM * sizeof(float));

    k_setup<<<577, 256>>>(Wn1, We1, batch_idx, edge_src);              // kernel #1
    k_scan<<<1, 512>>>();                                              // #2
    k_scatter<<<SC_BLOCKS, 256>>>();                                   // #3
    k_gemm_edge<<<444, 256, E_SMEM>>>(edge_attr, be1);                 // #4 (profiled)
    k_gemm_node<<<592, 256, SMEM_NODE>>>(x, batch_idx, bn1);           // #5
    k_finalize<<<64, 256>>>(Wn2, bn2, We2, be2, Wc, bc, out);          // #6
}

// round 16
// speedup vs baseline: 1.3188x; 1.0308x over previous
#include <cuda_runtime.h>
#include <cuda_bf16.h>
#include <cstdint>

// ---------------- problem constants (fixed shapes) ----------------
#define N_NODES 200000
#define N_EDGES 1000000
#define D_NODE  128
#define D_EDGE  64
#define HDIM    256
#define NGRAPH  512

#define MTILE 64
#define NODE_TILES (N_NODES / MTILE)   // 3125 (exact)
#define EDGE_TILES (N_EDGES / MTILE)   // 15625 (exact)
#define NCTA  128                      // output columns per CTA (HDIM split in 2)

#define E_RANKS 222                    // edge CTAs per nhalf (grid 444)
#define TPC_E   ((EDGE_TILES + E_RANKS - 1) / E_RANKS)   // 71
#define N_RANKS 296                    // node CTAs per nhalf (grid 592)
#define TPC_N   ((NODE_TILES + N_RANKS - 1) / N_RANKS)   // 11

// ---------------- scratch (device globals; no allocation) ----------------
__device__ float d_S_node[NGRAPH * HDIM];
__device__ float d_S_edge[NGRAPH * HDIM];
__device__ int   d_cnt_node[NGRAPH];
__device__ int   d_cnt_edge[NGRAPH];
__device__ unsigned short d_eb[N_EDGES];     // graph id per edge
__device__ int   d_esorted[N_EDGES];         // edge ids sorted by graph
__device__ int   d_cursor[NGRAPH];           // within-graph arrival offsets (pre-zeroed)
__device__ __nv_bfloat16 d_Wt_node[HDIM * D_NODE];  // [n][k]  (transposed, bf16)
__device__ __nv_bfloat16 d_Wt_edge[HDIM * D_EDGE];  // [n][k]

// ---------------- asm helpers ----------------
#define LDSM_X4(r0, r1, r2, r3, addr)                                          \
    asm volatile("ldmatrix.sync.aligned.m8n8.x4.shared.b16 {%0,%1,%2,%3}, [%4];" \
                 : "=r"(r0), "=r"(r1), "=r"(r2), "=r"(r3) : "r"(addr))

#define MMA16816(c0, c1, c2, c3, a0, a1, a2, a3, b0, b1)                       \
    asm volatile(                                                              \
        "mma.sync.aligned.m16n8k16.row.col.f32.bf16.bf16.f32 "                 \
        "{%0,%1,%2,%3}, {%4,%5,%6,%7}, {%8,%9}, {%0,%1,%2,%3};\n"              \
        : "+f"(c0), "+f"(c1), "+f"(c2), "+f"(c3)                               \
        : "r"(a0), "r"(a1), "r"(a2), "r"(a3), "r"(b0), "r"(b1))

// ---------------- launch #1: weight transpose + edge gid/hist + node counts
__global__ void k_setup(const float* __restrict__ Wn1, const float* __restrict__ We1,
                        const int* __restrict__ batch_idx, const int* __restrict__ edge_src)
{
    const int b = blockIdx.x;
    const int tid = threadIdx.x;
    if (b < 512) {
        __shared__ int h[NGRAPH];
        for (int j = tid; j < NGRAPH; j += 256) h[j] = 0;
        __syncthreads();
        int i = b * 256 + tid;
        for (int e = i; e < N_EDGES; e += 512 * 256) {
            int g = batch_idx[edge_src[e]];
            d_eb[e] = (unsigned short)g;
            atomicAdd(&h[g], 1);
        }
        __syncthreads();
        for (int j = tid; j < NGRAPH; j += 256)
            if (h[j]) atomicAdd(&d_cnt_edge[j], h[j]);
    } else if (b < 576) {
        int i = (b - 512) * 256 + tid;
        for (int j = i; j < HDIM * D_NODE; j += 64 * 256) {
            int n = j / D_NODE, k = j % D_NODE;
            d_Wt_node[j] = __float2bfloat16(Wn1[k * HDIM + n]);
        }
        for (int j = i; j < HDIM * D_EDGE; j += 64 * 256) {
            int n = j / D_EDGE, k = j % D_EDGE;
            d_Wt_edge[j] = __float2bfloat16(We1[k * HDIM + n]);
        }
    } else {
        // node counts via binary search over sorted batch_idx (covers ALL 512 graphs)
        for (int g = tid; g < NGRAPH; g += 256) {
            int lo = 0, hi = N_NODES;
            while (lo < hi) { int m = (lo + hi) >> 1; if (batch_idx[m] < g) lo = m + 1; else hi = m; }
            int lb0 = lo;
            lo = 0; hi = N_NODES;
            int g1 = g + 1;
            while (lo < hi) { int m = (lo + hi) >> 1; if (batch_idx[m] < g1) lo = m + 1; else hi = m; }
            d_cnt_node[g] = lo - lb0;
        }
    }
}

// ---------------- launch #3: counting-sort scatter with integrated scan ----
// Each block: smem histogram of its chunk; exclusive scan of GLOBAL d_cnt_edge
// (recomputed redundantly, cheap); reservation via atomicAdd on pre-zeroed
// d_cursor (within-graph arrival order); two-pass scatter. Contiguity preserved.
#define SC_BLOCKS 32
#define SC_CHUNK  (N_EDGES / SC_BLOCKS)   // 31250
__global__ void __launch_bounds__(256)
k_scatter() {
    __shared__ int h[NGRAPH];
    __shared__ int sscan[NGRAPH];
    __shared__ int base[NGRAPH];
    __shared__ int wsum[8];
    const int tid = threadIdx.x;
    const int lane = tid & 31, w = tid >> 5;
    const int e0 = blockIdx.x * SC_CHUNK;

    // exclusive scan of d_cnt_edge (512 entries, 2 per thread)
    int v0 = d_cnt_edge[2 * tid];
    int v1 = d_cnt_edge[2 * tid + 1];
    int tsum = v0 + v1;
    int s = tsum;
    #pragma unroll
    for (int o = 1; o < 32; o <<= 1) {
        int t = __shfl_up_sync(0xffffffffu, s, o);
        if (lane >= o) s += t;
    }
    if (lane == 31) wsum[w] = s;
    for (int j = tid; j < NGRAPH; j += 256) h[j] = 0;
    __syncthreads();
    if (tid == 0) {
        int run = 0;
        for (int i = 0; i < 8; i++) { int t = wsum[i]; wsum[i] = run; run += t; }
    }
    __syncthreads();
    int excl = s - tsum + wsum[w];
    sscan[2 * tid]     = excl;
    sscan[2 * tid + 1] = excl + v0;
    __syncthreads();

    // pass 1: chunk histogram
    for (int i = tid; i < SC_CHUNK; i += 256)
        atomicAdd(&h[(int)d_eb[e0 + i]], 1);
    __syncthreads();
    // reservation
    for (int j = tid; j < NGRAPH; j += 256) {
        int c = h[j];
        base[j] = sscan[j] + ((c > 0) ? atomicAdd(&d_cursor[j], c) : 0);
        h[j] = 0;
    }
    __syncthreads();
    // pass 2: scatter
    for (int i = tid; i < SC_CHUNK; i += 256) {
        int e = e0 + i;
        int g = (int)d_eb[e];
        int p = base[g] + atomicAdd(&h[g], 1);
        d_esorted[p] = e;
    }
}

// ---- flush helper: write racc to S and reset (warp-level, g warp-uniform) ----
#define FLUSH_RACC(Sbuf, g_run)                                                \
    do {                                                                       \
        if ((g_run) >= 0) {                                                    \
            if (lane < 4) {                                                    \
                _Pragma("unroll")                                              \
                for (int nf = 0; nf < 4; nf++) {                               \
                    float* dst = &Sbuf[(g_run) * HDIM + nbase + wn + nf * 8 + 2 * lane]; \
                    atomicAdd(dst,     racc0[nf]);                             \
                    atomicAdd(dst + 1, racc1[nf]);                             \
                }                                                              \
            }                                                                  \
            _Pragma("unroll")                                                  \
            for (int nf = 0; nf < 4; nf++) { racc0[nf] = 0.f; racc1[nf] = 0.f; } \
        }                                                                      \
    } while (0)

// ================= launch #4: EDGE GEMM — contiguous ranges + accum epilogue
#define EKPAD 72
#define E_AS_OFF 18432                       // Ws = 128*72*2
#define E_ASB    9216                        // one As buffer = 64*72*2
#define E_GID    36864                       // 2 x 64 ints
#define E_ES     37376                       // 2 x 64 ints
#define E_BIAS   37888                       // 128 floats
#define E_SMEM   38400

__global__ void __launch_bounds__(256, 3)
k_gemm_edge(const float* __restrict__ edge_attr, const float* __restrict__ be1)
{
    extern __shared__ char smem[];
    uint32_t sbase = (uint32_t)__cvta_generic_to_shared(smem);
    __nv_bfloat16* Ws = (__nv_bfloat16*)smem;
    __nv_bfloat16* As = (__nv_bfloat16*)(smem + E_AS_OFF);  // [2][64*72]
    int*   gid_s  = (int*)(smem + E_GID);                   // [2][64]
    int*   es_s   = (int*)(smem + E_ES);                    // [2][64]
    float* bias_s = (float*)(smem + E_BIAS);

    const int tid = threadIdx.x;
    const int rank  = blockIdx.x >> 1;
    const int nbase = (blockIdx.x & 1) * NCTA;
    const int t0   = rank * TPC_E;
    int tend = t0 + TPC_E; if (tend > EDGE_TILES) tend = EDGE_TILES;
    if (t0 >= tend) return;                 // CTA-uniform early exit

    const uint32_t* Wg32 = (const uint32_t*)d_Wt_edge;
    for (int j = tid; j < NCTA * 32; j += 256) {
        int n = j >> 5, k2 = j & 31;
        *(uint32_t*)&Ws[n * EKPAD + 2 * k2] = Wg32[(nbase + n) * 32 + k2];
    }
    if (tid < NCTA) bias_s[tid] = be1[nbase + tid];

    const int lane = tid & 31, warp = tid >> 5;
    const int wm = (warp & 1) * 32;
    const int wn = (warp >> 1) * 32;
    const int tig = lane & 3;

    const uint32_t a_off = (uint32_t)(((wm + (lane & 15)) * EKPAD + ((lane >> 4) << 3)) * 2);
    const int brow = (lane & 7) + ((lane >> 4) << 3);
    const int bkof = ((lane >> 3) & 1) << 3;
    const uint32_t b_addr0 = sbase + (uint32_t)(((wn + brow) * EKPAD + bkof) * 2);

    const int grow = tid >> 4;
    const int gq   = tid & 15;

    // ---- prologue: stage first tile into buffer 0 ----
    if (tid < MTILE) {
        int e = d_esorted[t0 * MTILE + tid];
        es_s[tid]  = e;
        gid_s[tid] = (int)d_eb[e];
    }
    __syncthreads();
    int glo_c = gid_s[0], ghi_c = gid_s[MTILE - 1];
    {
        float4 v[4];
        #pragma unroll
        for (int i = 0; i < 4; i++)
            v[i] = *(const float4*)(edge_attr + (size_t)es_s[grow + 16 * i] * 64 + gq * 4);
        #pragma unroll
        for (int i = 0; i < 4; i++) {
            __nv_bfloat162 p0 = __float22bfloat162_rn(make_float2(v[i].x, v[i].y));
            __nv_bfloat162 p1 = __float22bfloat162_rn(make_float2(v[i].z, v[i].w));
            uint2 pk; pk.x = *(uint32_t*)&p0; pk.y = *(uint32_t*)&p1;
            *(uint2*)&As[(grow + 16 * i) * EKPAD + gq * 4] = pk;
        }
    }

    float racc0[4] = {0.f, 0.f, 0.f, 0.f};
    float racc1[4] = {0.f, 0.f, 0.f, 0.f};
    int g_run = -1;

    int p = 0;
    for (int t = t0; t < tend; ++t) {
        const int q = p ^ 1;
        const bool has_next = (t + 1 < tend);

        if (has_next && tid < MTILE) {
            int e = d_esorted[(t + 1) * MTILE + tid];
            es_s[q * MTILE + tid]  = e;
            gid_s[q * MTILE + tid] = (int)d_eb[e];
        }
        __syncthreads();   // As[p] STS + es/gid[q] visible; reads of As[q] done

        int glo_n = 0, ghi_n = -1;
        if (has_next) {
            glo_n = gid_s[q * MTILE];
            ghi_n = gid_s[q * MTILE + MTILE - 1];
        }

        float4 v[4];
        if (has_next) {
            #pragma unroll
            for (int i = 0; i < 4; i++)
                v[i] = *(const float4*)(edge_attr +
                        (size_t)es_s[q * MTILE + grow + 16 * i] * 64 + gq * 4);
        }

        const uint32_t a_base = sbase + E_AS_OFF + (uint32_t)(p * E_ASB) + a_off;
        float c[2][4][4];
        #pragma unroll
        for (int mf = 0; mf < 2; mf++)
            #pragma unroll
            for (int nf = 0; nf < 4; nf++)
                #pragma unroll
                for (int r = 0; r < 4; r++) c[mf][nf][r] = 0.f;

        #pragma unroll
        for (int ks = 0; ks < 4; ks++) {
            const uint32_t koff = (uint32_t)(ks * 32);
            uint32_t a[2][4];
            LDSM_X4(a[0][0], a[0][1], a[0][2], a[0][3], a_base + koff);
            LDSM_X4(a[1][0], a[1][1], a[1][2], a[1][3], a_base + 16 * EKPAD * 2 + koff);
            #pragma unroll
            for (int nfp = 0; nfp < 2; nfp++) {
                uint32_t b0, b1, b2, b3;
                LDSM_X4(b0, b1, b2, b3,
                        b_addr0 + (uint32_t)(nfp * 16 * EKPAD * 2) + koff);
                const int nf = 2 * nfp;
                MMA16816(c[0][nf][0], c[0][nf][1], c[0][nf][2], c[0][nf][3],
                         a[0][0], a[0][1], a[0][2], a[0][3], b0, b1);
                MMA16816(c[1][nf][0], c[1][nf][1], c[1][nf][2], c[1][nf][3],
                         a[1][0], a[1][1], a[1][2], a[1][3], b0, b1);
                MMA16816(c[0][nf+1][0], c[0][nf+1][1], c[0][nf+1][2], c[0][nf+1][3],
                         a[0][0], a[0][1], a[0][2], a[0][3], b2, b3);
                MMA16816(c[1][nf+1][0], c[1][nf+1][1], c[1][nf+1][2], c[1][nf+1][3],
                         a[1][0], a[1][1], a[1][2], a[1][3], b2, b3);
            }
        }

        // ---- bias + relu ----
        #pragma unroll
        for (int nf = 0; nf < 4; nf++) {
            float b0 = bias_s[wn + nf * 8 + 2 * tig];
            float b1 = bias_s[wn + nf * 8 + 2 * tig + 1];
            #pragma unroll
            for (int mf = 0; mf < 2; mf++) {
                c[mf][nf][0] = fmaxf(c[mf][nf][0] + b0, 0.f);
                c[mf][nf][1] = fmaxf(c[mf][nf][1] + b1, 0.f);
                c[mf][nf][2] = fmaxf(c[mf][nf][2] + b0, 0.f);
                c[mf][nf][3] = fmaxf(c[mf][nf][3] + b1, 0.f);
            }
        }

        if (glo_c == ghi_c) {
            // ---- single-graph tile: reduce rows, accumulate into racc ----
            const int g = glo_c;
            if (g_run != g) { FLUSH_RACC(d_S_edge, g_run); g_run = g; }
            #pragma unroll
            for (int nf = 0; nf < 4; nf++) {
                float s0 = c[0][nf][0] + c[0][nf][2] + c[1][nf][0] + c[1][nf][2];
                float s1 = c[0][nf][1] + c[0][nf][3] + c[1][nf][1] + c[1][nf][3];
                #pragma unroll
                for (int o = 4; o <= 16; o <<= 1) {
                    s0 += __shfl_xor_sync(0xffffffffu, s0, o);
                    s1 += __shfl_xor_sync(0xffffffffu, s1, o);
                }
                racc0[nf] += s0;
                racc1[nf] += s1;
            }
        } else {
            // ---- mixed tile: flush, then masked per-graph direct atomics ----
            FLUSH_RACC(d_S_edge, g_run);
            g_run = -1;
            const int gID = lane >> 2;
            int gr00 = gid_s[p * MTILE + wm + gID];
            int gr01 = gid_s[p * MTILE + wm + 16 + gID];
            int gr10 = gid_s[p * MTILE + wm + gID + 8];
            int gr11 = gid_s[p * MTILE + wm + 16 + gID + 8];
            for (int g = glo_c; g <= ghi_c; ++g) {
                #pragma unroll
                for (int nf = 0; nf < 4; nf++) {
                    float s0 = 0.f, s1 = 0.f;
                    if (gr00 == g) { s0 += c[0][nf][0]; s1 += c[0][nf][1]; }
                    if (gr10 == g) { s0 += c[0][nf][2]; s1 += c[0][nf][3]; }
                    if (gr01 == g) { s0 += c[1][nf][0]; s1 += c[1][nf][1]; }
                    if (gr11 == g) { s0 += c[1][nf][2]; s1 += c[1][nf][3]; }
                    #pragma unroll
                    for (int o = 4; o <= 16; o <<= 1) {
                        s0 += __shfl_xor_sync(0xffffffffu, s0, o);
                        s1 += __shfl_xor_sync(0xffffffffu, s1, o);
                    }
                    if (lane < 4) {
                        float* dst = &d_S_edge[g * HDIM + nbase + wn + nf * 8 + 2 * lane];
                        atomicAdd(dst,     s0);
                        atomicAdd(dst + 1, s1);
                    }
                }
            }
        }

        if (has_next) {
            #pragma unroll
            for (int i = 0; i < 4; i++) {
                __nv_bfloat162 p0 = __float22bfloat162_rn(make_float2(v[i].x, v[i].y));
                __nv_bfloat162 p1 = __float22bfloat162_rn(make_float2(v[i].z, v[i].w));
                uint2 pk; pk.x = *(uint32_t*)&p0; pk.y = *(uint32_t*)&p1;
                *(uint2*)&As[q * (E_ASB / 2) + (grow + 16 * i) * EKPAD + gq * 4] = pk;
            }
        }

        glo_c = glo_n; ghi_c = ghi_n;
        p = q;
    }
    FLUSH_RACC(d_S_edge, g_run);
}

// ================= launch #2: NODE GEMM — contiguous ranges + accum epilogue
#define NKPAD (D_NODE + 8)
#define N_WS_BYTES (NCTA * NKPAD * 2)            // 34816
#define N_AS_BYTES (MTILE * NKPAD * 2)           // 17408
#define SMEM_NODE (N_WS_BYTES + N_AS_BYTES + 1024)   // 53248

__global__ void __launch_bounds__(256, 4)
k_gemm_node(const float* __restrict__ x, const int* __restrict__ batch_idx,
            const float* __restrict__ bn1)
{
    extern __shared__ char smem[];
    uint32_t sbase = (uint32_t)__cvta_generic_to_shared(smem);
    __nv_bfloat16* Ws = (__nv_bfloat16*)(smem);
    __nv_bfloat16* As = (__nv_bfloat16*)(smem + N_WS_BYTES);
    int*   gid_s  = (int*)(smem + N_WS_BYTES + N_AS_BYTES);
    float* bias_s = (float*)(smem + N_WS_BYTES + N_AS_BYTES + 512);

    const int tid = threadIdx.x;
    const int rank  = blockIdx.x >> 1;
    const int nbase = (blockIdx.x & 1) * NCTA;
    const int t0   = rank * TPC_N;
    int tend = t0 + TPC_N; if (tend > NODE_TILES) tend = NODE_TILES;
    if (t0 >= tend) return;

    const uint32_t* Wg32 = (const uint32_t*)d_Wt_node;
    for (int j = tid; j < NCTA * 64; j += 256) {
        int n = j >> 6, k2 = j & 63;
        *(uint32_t*)&Ws[n * NKPAD + 2 * k2] = Wg32[(nbase + n) * 64 + k2];
    }
    if (tid < NCTA) bias_s[tid] = bn1[nbase + tid];
    __syncthreads();

    const int lane = tid & 31, warp = tid >> 5;
    const int wm = (warp & 1) * 32;
    const int wn = (warp >> 1) * 32;
    const int tig = lane & 3;

    const uint32_t a_addr0 = sbase + N_WS_BYTES +
        (uint32_t)(((wm + (lane & 15)) * NKPAD + ((lane >> 4) << 3)) * 2);
    const uint32_t a_addr1 = a_addr0 + (uint32_t)(16 * NKPAD * 2);
    const int brow = (lane & 7) + ((lane >> 4) << 3);
    const int bkof = ((lane >> 3) & 1) << 3;
    const uint32_t b_addr0 = sbase + (uint32_t)(((wn + brow) * NKPAD + bkof) * 2);

    float racc0[4] = {0.f, 0.f, 0.f, 0.f};
    float racc1[4] = {0.f, 0.f, 0.f, 0.f};
    int g_run = -1;

    for (int t = t0; t < tend; ++t) {
        const int r0 = t * MTILE;

        __syncthreads();
        if (tid < MTILE) gid_s[tid] = batch_idx[r0 + tid];
        __syncthreads();

        #pragma unroll
        for (int base = 0; base < 8; base += 4) {
            float4 v[4];
            #pragma unroll
            for (int i = 0; i < 4; i++) {
                int j = tid + (base + i) * 256;
                int r = j >> 5, q = j & 31;
                v[i] = *(const float4*)(x + (size_t)(r0 + r) * D_NODE + q * 4);
            }
            #pragma unroll
            for (int i = 0; i < 4; i++) {
                int j = tid + (base + i) * 256;
                int r = j >> 5, q = j & 31;
                __nv_bfloat162 p0 = __float22bfloat162_rn(make_float2(v[i].x, v[i].y));
                __nv_bfloat162 p1 = __float22bfloat162_rn(make_float2(v[i].z, v[i].w));
                *(__nv_bfloat162*)&As[r * NKPAD + q * 4]     = p0;
                *(__nv_bfloat162*)&As[r * NKPAD + q * 4 + 2] = p1;
            }
        }
        __syncthreads();

        const int glo = gid_s[0];
        const int ghi = gid_s[MTILE - 1];

        float c[2][4][4];
        #pragma unroll
        for (int mf = 0; mf < 2; mf++)
            #pragma unroll
            for (int nf = 0; nf < 4; nf++)
                #pragma unroll
                for (int r = 0; r < 4; r++) c[mf][nf][r] = 0.f;

        #pragma unroll
        for (int ks = 0; ks < 8; ks++) {
            const uint32_t koff = (uint32_t)(ks * 32);
            uint32_t a[2][4];
            LDSM_X4(a[0][0], a[0][1], a[0][2], a[0][3], a_addr0 + koff);
            LDSM_X4(a[1][0], a[1][1], a[1][2], a[1][3], a_addr1 + koff);
            #pragma unroll
            for (int nfp = 0; nfp < 2; nfp++) {
                uint32_t b0, b1, b2, b3;
                LDSM_X4(b0, b1, b2, b3,
                        b_addr0 + (uint32_t)(nfp * 16 * NKPAD * 2) + koff);
                const int nf = 2 * nfp;
                MMA16816(c[0][nf][0], c[0][nf][1], c[0][nf][2], c[0][nf][3],
                         a[0][0], a[0][1], a[0][2], a[0][3], b0, b1);
                MMA16816(c[1][nf][0], c[1][nf][1], c[1][nf][2], c[1][nf][3],
                         a[1][0], a[1][1], a[1][2], a[1][3], b0, b1);
                MMA16816(c[0][nf+1][0], c[0][nf+1][1], c[0][nf+1][2], c[0][nf+1][3],
                         a[0][0], a[0][1], a[0][2], a[0][3], b2, b3);
                MMA16816(c[1][nf+1][0], c[1][nf+1][1], c[1][nf+1][2], c[1][nf+1][3],
                         a[1][0], a[1][1], a[1][2], a[1][3], b2, b3);
            }
        }

        #pragma unroll
        for (int nf = 0; nf < 4; nf++) {
            float b0 = bias_s[wn + nf * 8 + 2 * tig];
            float b1 = bias_s[wn + nf * 8 + 2 * tig + 1];
            #pragma unroll
            for (int mf = 0; mf < 2; mf++) {
                c[mf][nf][0] = fmaxf(c[mf][nf][0] + b0, 0.f);
                c[mf][nf][1] = fmaxf(c[mf][nf][1] + b1, 0.f);
                c[mf][nf][2] = fmaxf(c[mf][nf][2] + b0, 0.f);
                c[mf][nf][3] = fmaxf(c[mf][nf][3] + b1, 0.f);
            }
        }

        if (glo == ghi) {
            const int g = glo;
            if (g_run != g) { FLUSH_RACC(d_S_node, g_run); g_run = g; }
            #pragma unroll
            for (int nf = 0; nf < 4; nf++) {
                float s0 = c[0][nf][0] + c[0][nf][2] + c[1][nf][0] + c[1][nf][2];
                float s1 = c[0][nf][1] + c[0][nf][3] + c[1][nf][1] + c[1][nf][3];
                #pragma unroll
                for (int o = 4; o <= 16; o <<= 1) {
                    s0 += __shfl_xor_sync(0xffffffffu, s0, o);
                    s1 += __shfl_xor_sync(0xffffffffu, s1, o);
                }
                racc0[nf] += s0;
                racc1[nf] += s1;
            }
        } else {
            FLUSH_RACC(d_S_node, g_run);
            g_run = -1;
            const int gID = lane >> 2;
            int gr00 = gid_s[wm + gID];
            int gr01 = gid_s[wm + 16 + gID];
            int gr10 = gid_s[wm + gID + 8];
            int gr11 = gid_s[wm + 16 + gID + 8];
            for (int g = glo; g <= ghi; ++g) {
                #pragma unroll
                for (int nf = 0; nf < 4; nf++) {
                    float s0 = 0.f, s1 = 0.f;
                    if (gr00 == g) { s0 += c[0][nf][0]; s1 += c[0][nf][1]; }
                    if (gr10 == g) { s0 += c[0][nf][2]; s1 += c[0][nf][3]; }
                    if (gr01 == g) { s0 += c[1][nf][0]; s1 += c[1][nf][1]; }
                    if (gr11 == g) { s0 += c[1][nf][2]; s1 += c[1][nf][3]; }
                    #pragma unroll
                    for (int o = 4; o <= 16; o <<= 1) {
                        s0 += __shfl_xor_sync(0xffffffffu, s0, o);
                        s1 += __shfl_xor_sync(0xffffffffu, s1, o);
                    }
                    if (lane < 4) {
                        float* dst = &d_S_node[g * HDIM + nbase + wn + nf * 8 + 2 * lane];
                        atomicAdd(dst,     s0);
                        atomicAdd(dst + 1, s1);
                    }
                }
            }
        }
    }
    FLUSH_RACC(d_S_node, g_run);
}

// ---------------- launch #5: means -> layer-2 -> combine ------------------
__global__ void __launch_bounds__(256)
k_finalize(const float* __restrict__ Wn2, const float* __restrict__ bn2,
           const float* __restrict__ We2, const float* __restrict__ be2,
           const float* __restrict__ Wc,  const float* __restrict__ bc,
           float* __restrict__ out)
{
    __shared__ float mn[8][HDIM], me[8][HDIM], gr[8][HDIM];
    __shared__ int fn[8], fe[8];
    const int tid = threadIdx.x;
    const int gbase = blockIdx.x * 8;

    #pragma unroll
    for (int gg = 0; gg < 8; gg++) {
        int g = gbase + gg;
        int cn = d_cnt_node[g], ce = d_cnt_edge[g];
        if (tid == 0) { fn[gg] = cn; fe[gg] = ce; }
        mn[gg][tid] = (cn > 0) ? d_S_node[g * HDIM + tid] / (float)cn : 0.f;
        me[gg][tid] = (ce > 0) ? d_S_edge[g * HDIM + tid] / (float)ce : 0.f;
    }
    __syncthreads();

    float an[8], ae[8];
    #pragma unroll
    for (int gg = 0; gg < 8; gg++) { an[gg] = 0.f; ae[gg] = 0.f; }
    for (int j = 0; j < HDIM; j++) {
        float w1 = Wn2[j * HDIM + tid];
        float w2 = We2[j * HDIM + tid];
        #pragma unroll
        for (int gg = 0; gg < 8; gg++) {
            an[gg] += mn[gg][j] * w1;
            ae[gg] += me[gg][j] * w2;
        }
    }
    float b2n = bn2[tid], b2e = be2[tid];
    #pragma unroll
    for (int gg = 0; gg < 8; gg++) {
        float nr = (fn[gg] > 0) ? an[gg] + b2n : 0.f;
        float er = (fe[gg] > 0) ? ae[gg] + b2e : 0.f;
        gr[gg][tid] = nr + er;
    }
    __syncthreads();

    float ao[8];
    #pragma unroll
    for (int gg = 0; gg < 8; gg++) ao[gg] = 0.f;
    for (int j = 0; j < HDIM; j++) {
        float w = Wc[j * HDIM + tid];
        #pragma unroll
        for (int gg = 0; gg < 8; gg++) ao[gg] += gr[gg][j] * w;
    }
    float bcv = bc[tid];
    #pragma unroll
    for (int gg = 0; gg < 8; gg++)
        out[(gbase + gg) * HDIM + tid] = ao[gg] + bcv;
}

// ---------------- launch ----------------
extern "C" void kernel_launch(void* const* d_in, const int* in_sizes, int n_in,
                              void* d_out, int out_size)
{
    const float* x         = (const float*)d_in[0];
    const float* edge_attr = (const float*)d_in[1];
    const int*   batch_idx = (const int*)d_in[2];
    const int*   edge_src  = (const int*)d_in[3];
    const float* Wn1 = (const float*)d_in[4];
    const float* bn1 = (const float*)d_in[5];
    const float* Wn2 = (const float*)d_in[6];
    const float* bn2 = (const float*)d_in[7];
    const float* We1 = (const float*)d_in[8];
    const float* be1 = (const float*)d_in[9];
    const float* We2 = (const float*)d_in[10];
    const float* be2 = (const float*)d_in[11];
    const float* Wc  = (const float*)d_in[12];
    const float* bc  = (const float*)d_in[13];
    float* out = (float*)d_out;

    (void)in_sizes; (void)n_in; (void)out_size;

    cudaFuncSetAttribute(k_gemm_edge, cudaFuncAttributeMaxDynamicSharedMemorySize, E_SMEM);
    cudaFuncSetAttribute(k_gemm_node, cudaFuncAttributeMaxDynamicSharedMemorySize, SMEM_NODE);

    // zero scratch via memset nodes (not kernel launches)
    void* p;
    cudaGetSymbolAddress(&p, d_cnt_edge);  cudaMemsetAsync(p, 0, NGRAPH * sizeof(int));
    cudaGetSymbolAddress(&p, d_cursor);    cudaMemsetAsync(p, 0, NGRAPH * sizeof(int));
    cudaGetSymbolAddress(&p, d_S_node);    cudaMemsetAsync(p, 0, NGRAPH * HDIM * sizeof(float));
    cudaGetSymbolAddress(&p, d_S_edge);    cudaMemsetAsync(p, 0, NGRAPH * HDIM * sizeof(float));

    k_setup<<<577, 256>>>(Wn1, We1, batch_idx, edge_src);              // kernel #1
    k_gemm_node<<<592, 256, SMEM_NODE>>>(x, batch_idx, bn1);           // #2 (indep of scatter)
    k_scatter<<<SC_BLOCKS, 256>>>();                                   // #3 (scan folded in)
    k_gemm_edge<<<444, 256, E_SMEM>>>(edge_attr, be1);                 // #4 (profiled)
    k_finalize<<<64, 256>>>(Wn2, bn2, We2, be2, Wc, bc, out);          // #5
}

// round 17
// speedup vs baseline: 1.3877x; 1.0523x over previous
#include <cuda_runtime.h>
#include <cuda_bf16.h>
#include <cstdint>

// ---------------- problem constants (fixed shapes) ----------------
#define N_NODES 200000
#define N_EDGES 1000000
#define D_NODE  128
#define D_EDGE  64
#define HDIM    256
#define NGRAPH  512

#define MTILE 64
#define NODE_TILES (N_NODES / MTILE)   // 3125 (exact)
#define EDGE_TILES (N_EDGES / MTILE)   // 15625 (exact)
#define NCTA  128                      // output columns per CTA (HDIM split in 2)

#define E_RANKS 222                    // edge CTAs per nhalf (grid 444)
#define TPC_E   ((EDGE_TILES + E_RANKS - 1) / E_RANKS)   // 71
#define N_RANKS 296                    // node CTAs per nhalf (grid 592)
#define TPC_N   ((NODE_TILES + N_RANKS - 1) / N_RANKS)   // 11

// ---------------- scratch (device globals; no allocation) ----------------
__device__ float d_S_node[NGRAPH * HDIM];
__device__ float d_S_edge[NGRAPH * HDIM];
__device__ int   d_cnt_node[NGRAPH];
__device__ int   d_cnt_edge[NGRAPH];
__device__ unsigned short d_eb[N_EDGES];     // graph id per edge
__device__ int   d_esorted[N_EDGES];         // edge ids sorted by graph
__device__ int   d_cursor[NGRAPH];           // within-graph arrival offsets (pre-zeroed)
__device__ __nv_bfloat16 d_Wt_node[HDIM * D_NODE];  // [n][k]  (transposed, bf16)
__device__ __nv_bfloat16 d_Wt_edge[HDIM * D_EDGE];  // [n][k]

// ---------------- asm helpers ----------------
#define LDSM_X4(r0, r1, r2, r3, addr)                                          \
    asm volatile("ldmatrix.sync.aligned.m8n8.x4.shared.b16 {%0,%1,%2,%3}, [%4];" \
                 : "=r"(r0), "=r"(r1), "=r"(r2), "=r"(r3) : "r"(addr))

#define MMA16816(c0, c1, c2, c3, a0, a1, a2, a3, b0, b1)                       \
    asm volatile(                                                              \
        "mma.sync.aligned.m16n8k16.row.col.f32.bf16.bf16.f32 "                 \
        "{%0,%1,%2,%3}, {%4,%5,%6,%7}, {%8,%9}, {%0,%1,%2,%3};\n"              \
        : "+f"(c0), "+f"(c1), "+f"(c2), "+f"(c3)                               \
        : "r"(a0), "r"(a1), "r"(a2), "r"(a3), "r"(b0), "r"(b1))

// ---------------- launch #1: weight transpose + edge gid/hist + node counts
__global__ void k_setup(const float* __restrict__ Wn1, const float* __restrict__ We1,
                        const int* __restrict__ batch_idx, const int* __restrict__ edge_src)
{
    const int b = blockIdx.x;
    const int tid = threadIdx.x;
    if (b < 512) {
        __shared__ int h[NGRAPH];
        for (int j = tid; j < NGRAPH; j += 256) h[j] = 0;
        __syncthreads();
        int i = b * 256 + tid;
        for (int e = i; e < N_EDGES; e += 512 * 256) {
            int g = batch_idx[edge_src[e]];
            d_eb[e] = (unsigned short)g;
            atomicAdd(&h[g], 1);
        }
        __syncthreads();
        for (int j = tid; j < NGRAPH; j += 256)
            if (h[j]) atomicAdd(&d_cnt_edge[j], h[j]);
    } else if (b < 576) {
        int i = (b - 512) * 256 + tid;
        for (int j = i; j < HDIM * D_NODE; j += 64 * 256) {
            int n = j / D_NODE, k = j % D_NODE;
            d_Wt_node[j] = __float2bfloat16(Wn1[k * HDIM + n]);
        }
        for (int j = i; j < HDIM * D_EDGE; j += 64 * 256) {
            int n = j / D_EDGE, k = j % D_EDGE;
            d_Wt_edge[j] = __float2bfloat16(We1[k * HDIM + n]);
        }
    } else {
        // node counts via binary search over sorted batch_idx (covers ALL 512 graphs)
        for (int g = tid; g < NGRAPH; g += 256) {
            int lo = 0, hi = N_NODES;
            while (lo < hi) { int m = (lo + hi) >> 1; if (batch_idx[m] < g) lo = m + 1; else hi = m; }
            int lb0 = lo;
            lo = 0; hi = N_NODES;
            int g1 = g + 1;
            while (lo < hi) { int m = (lo + hi) >> 1; if (batch_idx[m] < g1) lo = m + 1; else hi = m; }
            d_cnt_node[g] = lo - lb0;
        }
    }
}

// ---------------- launch #2: counting-sort scatter, smem-cached chunk ------
// Each block caches its d_eb chunk in smem (one gmem pass instead of three),
// computes chunk histogram, redundantly scans the global d_cnt_edge, reserves
// per-graph space via atomicAdd on pre-zeroed d_cursor, then scatters.
#define SC_BLOCKS 64
#define SC_CHUNK  (N_EDGES / SC_BLOCKS)   // 15625
__global__ void __launch_bounds__(256)
k_scatter() {
    __shared__ unsigned short ebc[SC_CHUNK];   // 31250 B
    __shared__ int h[NGRAPH];
    __shared__ int sscan[NGRAPH];
    __shared__ int base[NGRAPH];
    __shared__ int wsum[8];
    const int tid = threadIdx.x;
    const int lane = tid & 31, w = tid >> 5;
    const int e0 = blockIdx.x * SC_CHUNK;

    // cache chunk + zero histogram
    for (int i = tid; i < SC_CHUNK; i += 256) ebc[i] = d_eb[e0 + i];
    for (int j = tid; j < NGRAPH; j += 256) h[j] = 0;

    // exclusive scan of global d_cnt_edge (512 entries, 2 per thread)
    int v0 = d_cnt_edge[2 * tid];
    int v1 = d_cnt_edge[2 * tid + 1];
    int tsum = v0 + v1;
    int s = tsum;
    #pragma unroll
    for (int o = 1; o < 32; o <<= 1) {
        int t = __shfl_up_sync(0xffffffffu, s, o);
        if (lane >= o) s += t;
    }
    if (lane == 31) wsum[w] = s;
    __syncthreads();
    if (tid == 0) {
        int run = 0;
        for (int i = 0; i < 8; i++) { int t = wsum[i]; wsum[i] = run; run += t; }
    }
    __syncthreads();
    int excl = s - tsum + wsum[w];
    sscan[2 * tid]     = excl;
    sscan[2 * tid + 1] = excl + v0;
    __syncthreads();

    // pass 1: chunk histogram (from smem cache)
    for (int i = tid; i < SC_CHUNK; i += 256)
        atomicAdd(&h[(int)ebc[i]], 1);
    __syncthreads();
    // reservation
    for (int j = tid; j < NGRAPH; j += 256) {
        int c = h[j];
        base[j] = sscan[j] + ((c > 0) ? atomicAdd(&d_cursor[j], c) : 0);
        h[j] = 0;
    }
    __syncthreads();
    // pass 2: scatter (from smem cache)
    for (int i = tid; i < SC_CHUNK; i += 256) {
        int g = (int)ebc[i];
        int p = base[g] + atomicAdd(&h[g], 1);
        d_esorted[p] = e0 + i;
    }
}

// ---- flush helper: write racc to S and reset (warp-level, g warp-uniform) ----
#define FLUSH_RACC(Sbuf, g_run)                                                \
    do {                                                                       \
        if ((g_run) >= 0) {                                                    \
            if (lane < 4) {                                                    \
                _Pragma("unroll")                                              \
                for (int nf = 0; nf < 4; nf++) {                               \
                    float* dst = &Sbuf[(g_run) * HDIM + nbase + wn + nf * 8 + 2 * lane]; \
                    atomicAdd(dst,     racc0[nf]);                             \
                    atomicAdd(dst + 1, racc1[nf]);                             \
                }                                                              \
            }                                                                  \
            _Pragma("unroll")                                                  \
            for (int nf = 0; nf < 4; nf++) { racc0[nf] = 0.f; racc1[nf] = 0.f; } \
        }                                                                      \
    } while (0)

// ================= launch #3: EDGE GEMM (R15 config, measured 180.7us) =====
#define EKPAD 72
#define E_AS_OFF 18432                       // Ws = 128*72*2
#define E_ASB    9216                        // one As buffer = 64*72*2
#define E_GID    36864                       // 2 x 64 ints
#define E_ES     37376                       // 2 x 64 ints
#define E_BIAS   37888                       // 128 floats
#define E_SMEM   38400

__global__ void __launch_bounds__(256, 3)
k_gemm_edge(const float* __restrict__ edge_attr, const float* __restrict__ be1)
{
    extern __shared__ char smem[];
    uint32_t sbase = (uint32_t)__cvta_generic_to_shared(smem);
    __nv_bfloat16* Ws = (__nv_bfloat16*)smem;
    __nv_bfloat16* As = (__nv_bfloat16*)(smem + E_AS_OFF);  // [2][64*72]
    int*   gid_s  = (int*)(smem + E_GID);                   // [2][64]
    int*   es_s   = (int*)(smem + E_ES);                    // [2][64]
    float* bias_s = (float*)(smem + E_BIAS);

    const int tid = threadIdx.x;
    const int rank  = blockIdx.x >> 1;
    const int nbase = (blockIdx.x & 1) * NCTA;
    const int t0   = rank * TPC_E;
    int tend = t0 + TPC_E; if (tend > EDGE_TILES) tend = EDGE_TILES;
    if (t0 >= tend) return;                 // CTA-uniform early exit

    const uint32_t* Wg32 = (const uint32_t*)d_Wt_edge;
    for (int j = tid; j < NCTA * 32; j += 256) {
        int n = j >> 5, k2 = j & 31;
        *(uint32_t*)&Ws[n * EKPAD + 2 * k2] = Wg32[(nbase + n) * 32 + k2];
    }
    if (tid < NCTA) bias_s[tid] = be1[nbase + tid];

    const int lane = tid & 31, warp = tid >> 5;
    const int wm = (warp & 1) * 32;
    const int wn = (warp >> 1) * 32;
    const int tig = lane & 3;

    const uint32_t a_off = (uint32_t)(((wm + (lane & 15)) * EKPAD + ((lane >> 4) << 3)) * 2);
    const int brow = (lane & 7) + ((lane >> 4) << 3);
    const int bkof = ((lane >> 3) & 1) << 3;
    const uint32_t b_addr0 = sbase + (uint32_t)(((wn + brow) * EKPAD + bkof) * 2);

    const int grow = tid >> 4;
    const int gq   = tid & 15;

    // ---- prologue: stage first tile into buffer 0 ----
    if (tid < MTILE) {
        int e = d_esorted[t0 * MTILE + tid];
        es_s[tid]  = e;
        gid_s[tid] = (int)d_eb[e];
    }
    __syncthreads();
    int glo_c = gid_s[0], ghi_c = gid_s[MTILE - 1];
    {
        float4 v[4];
        #pragma unroll
        for (int i = 0; i < 4; i++)
            v[i] = *(const float4*)(edge_attr + (size_t)es_s[grow + 16 * i] * 64 + gq * 4);
        #pragma unroll
        for (int i = 0; i < 4; i++) {
            __nv_bfloat162 p0 = __float22bfloat162_rn(make_float2(v[i].x, v[i].y));
            __nv_bfloat162 p1 = __float22bfloat162_rn(make_float2(v[i].z, v[i].w));
            uint2 pk; pk.x = *(uint32_t*)&p0; pk.y = *(uint32_t*)&p1;
            *(uint2*)&As[(grow + 16 * i) * EKPAD + gq * 4] = pk;
        }
    }

    float racc0[4] = {0.f, 0.f, 0.f, 0.f};
    float racc1[4] = {0.f, 0.f, 0.f, 0.f};
    int g_run = -1;

    int p = 0;
    for (int t = t0; t < tend; ++t) {
        const int q = p ^ 1;
        const bool has_next = (t + 1 < tend);

        if (has_next && tid < MTILE) {
            int e = d_esorted[(t + 1) * MTILE + tid];
            es_s[q * MTILE + tid]  = e;
            gid_s[q * MTILE + tid] = (int)d_eb[e];
        }
        __syncthreads();   // As[p] STS + es/gid[q] visible; reads of As[q] done

        int glo_n = 0, ghi_n = -1;
        if (has_next) {
            glo_n = gid_s[q * MTILE];
            ghi_n = gid_s[q * MTILE + MTILE - 1];
        }

        float4 v[4];
        if (has_next) {
            #pragma unroll
            for (int i = 0; i < 4; i++)
                v[i] = *(const float4*)(edge_attr +
                        (size_t)es_s[q * MTILE + grow + 16 * i] * 64 + gq * 4);
        }

        const uint32_t a_base = sbase + E_AS_OFF + (uint32_t)(p * E_ASB) + a_off;
        float c[2][4][4];
        #pragma unroll
        for (int mf = 0; mf < 2; mf++)
            #pragma unroll
            for (int nf = 0; nf < 4; nf++)
                #pragma unroll
                for (int r = 0; r < 4; r++) c[mf][nf][r] = 0.f;

        #pragma unroll
        for (int ks = 0; ks < 4; ks++) {
            const uint32_t koff = (uint32_t)(ks * 32);
            uint32_t a[2][4];
            LDSM_X4(a[0][0], a[0][1], a[0][2], a[0][3], a_base + koff);
            LDSM_X4(a[1][0], a[1][1], a[1][2], a[1][3], a_base + 16 * EKPAD * 2 + koff);
            #pragma unroll
            for (int nfp = 0; nfp < 2; nfp++) {
                uint32_t b0, b1, b2, b3;
                LDSM_X4(b0, b1, b2, b3,
                        b_addr0 + (uint32_t)(nfp * 16 * EKPAD * 2) + koff);
                const int nf = 2 * nfp;
                MMA16816(c[0][nf][0], c[0][nf][1], c[0][nf][2], c[0][nf][3],
                         a[0][0], a[0][1], a[0][2], a[0][3], b0, b1);
                MMA16816(c[1][nf][0], c[1][nf][1], c[1][nf][2], c[1][nf][3],
                         a[1][0], a[1][1], a[1][2], a[1][3], b0, b1);
                MMA16816(c[0][nf+1][0], c[0][nf+1][1], c[0][nf+1][2], c[0][nf+1][3],
                         a[0][0], a[0][1], a[0][2], a[0][3], b2, b3);
                MMA16816(c[1][nf+1][0], c[1][nf+1][1], c[1][nf+1][2], c[1][nf+1][3],
                         a[1][0], a[1][1], a[1][2], a[1][3], b2, b3);
            }
        }

        // ---- bias + relu ----
        #pragma unroll
        for (int nf = 0; nf < 4; nf++) {
            float b0 = bias_s[wn + nf * 8 + 2 * tig];
            float b1 = bias_s[wn + nf * 8 + 2 * tig + 1];
            #pragma unroll
            for (int mf = 0; mf < 2; mf++) {
                c[mf][nf][0] = fmaxf(c[mf][nf][0] + b0, 0.f);
                c[mf][nf][1] = fmaxf(c[mf][nf][1] + b1, 0.f);
                c[mf][nf][2] = fmaxf(c[mf][nf][2] + b0, 0.f);
                c[mf][nf][3] = fmaxf(c[mf][nf][3] + b1, 0.f);
            }
        }

        if (glo_c == ghi_c) {
            const int g = glo_c;
            if (g_run != g) { FLUSH_RACC(d_S_edge, g_run); g_run = g; }
            #pragma unroll
            for (int nf = 0; nf < 4; nf++) {
                float s0 = c[0][nf][0] + c[0][nf][2] + c[1][nf][0] + c[1][nf][2];
                float s1 = c[0][nf][1] + c[0][nf][3] + c[1][nf][1] + c[1][nf][3];
                #pragma unroll
                for (int o = 4; o <= 16; o <<= 1) {
                    s0 += __shfl_xor_sync(0xffffffffu, s0, o);
                    s1 += __shfl_xor_sync(0xffffffffu, s1, o);
                }
                racc0[nf] += s0;
                racc1[nf] += s1;
            }
        } else {
            FLUSH_RACC(d_S_edge, g_run);
            g_run = -1;
            const int gID = lane >> 2;
            int gr00 = gid_s[p * MTILE + wm + gID];
            int gr01 = gid_s[p * MTILE + wm + 16 + gID];
            int gr10 = gid_s[p * MTILE + wm + gID + 8];
            int gr11 = gid_s[p * MTILE + wm + 16 + gID + 8];
            for (int g = glo_c; g <= ghi_c; ++g) {
                #pragma unroll
                for (int nf = 0; nf < 4; nf++) {
                    float s0 = 0.f, s1 = 0.f;
                    if (gr00 == g) { s0 += c[0][nf][0]; s1 += c[0][nf][1]; }
                    if (gr10 == g) { s0 += c[0][nf][2]; s1 += c[0][nf][3]; }
                    if (gr01 == g) { s0 += c[1][nf][0]; s1 += c[1][nf][1]; }
                    if (gr11 == g) { s0 += c[1][nf][2]; s1 += c[1][nf][3]; }
                    #pragma unroll
                    for (int o = 4; o <= 16; o <<= 1) {
                        s0 += __shfl_xor_sync(0xffffffffu, s0, o);
                        s1 += __shfl_xor_sync(0xffffffffu, s1, o);
                    }
                    if (lane < 4) {
                        float* dst = &d_S_edge[g * HDIM + nbase + wn + nf * 8 + 2 * lane];
                        atomicAdd(dst,     s0);
                        atomicAdd(dst + 1, s1);
                    }
                }
            }
        }

        if (has_next) {
            #pragma unroll
            for (int i = 0; i < 4; i++) {
                __nv_bfloat162 p0 = __float22bfloat162_rn(make_float2(v[i].x, v[i].y));
                __nv_bfloat162 p1 = __float22bfloat162_rn(make_float2(v[i].z, v[i].w));
                uint2 pk; pk.x = *(uint32_t*)&p0; pk.y = *(uint32_t*)&p1;
                *(uint2*)&As[q * (E_ASB / 2) + (grow + 16 * i) * EKPAD + gq * 4] = pk;
            }
        }

        glo_c = glo_n; ghi_c = ghi_n;
        p = q;
    }
    FLUSH_RACC(d_S_edge, g_run);
}

// ================= launch #4: NODE GEMM (R15 config — PROFILED SLOT) =======
#define NKPAD (D_NODE + 8)
#define N_WS_BYTES (NCTA * NKPAD * 2)            // 34816
#define N_AS_BYTES (MTILE * NKPAD * 2)           // 17408
#define SMEM_NODE (N_WS_BYTES + N_AS_BYTES + 1024)   // 53248

__global__ void __launch_bounds__(256, 4)
k_gemm_node(const float* __restrict__ x, const int* __restrict__ batch_idx,
            const float* __restrict__ bn1)
{
    extern __shared__ char smem[];
    uint32_t sbase = (uint32_t)__cvta_generic_to_shared(smem);
    __nv_bfloat16* Ws = (__nv_bfloat16*)(smem);
    __nv_bfloat16* As = (__nv_bfloat16*)(smem + N_WS_BYTES);
    int*   gid_s  = (int*)(smem + N_WS_BYTES + N_AS_BYTES);
    float* bias_s = (float*)(smem + N_WS_BYTES + N_AS_BYTES + 512);

    const int tid = threadIdx.x;
    const int rank  = blockIdx.x >> 1;
    const int nbase = (blockIdx.x & 1) * NCTA;
    const int t0   = rank * TPC_N;
    int tend = t0 + TPC_N; if (tend > NODE_TILES) tend = NODE_TILES;
    if (t0 >= tend) return;

    const uint32_t* Wg32 = (const uint32_t*)d_Wt_node;
    for (int j = tid; j < NCTA * 64; j += 256) {
        int n = j >> 6, k2 = j & 63;
        *(uint32_t*)&Ws[n * NKPAD + 2 * k2] = Wg32[(nbase + n) * 64 + k2];
    }
    if (tid < NCTA) bias_s[tid] = bn1[nbase + tid];
    __syncthreads();

    const int lane = tid & 31, warp = tid >> 5;
    const int wm = (warp & 1) * 32;
    const int wn = (warp >> 1) * 32;
    const int tig = lane & 3;

    const uint32_t a_addr0 = sbase + N_WS_BYTES +
        (uint32_t)(((wm + (lane & 15)) * NKPAD + ((lane >> 4) << 3)) * 2);
    const uint32_t a_addr1 = a_addr0 + (uint32_t)(16 * NKPAD * 2);
    const int brow = (lane & 7) + ((lane >> 4) << 3);
    const int bkof = ((lane >> 3) & 1) << 3;
    const uint32_t b_addr0 = sbase + (uint32_t)(((wn + brow) * NKPAD + bkof) * 2);

    float racc0[4] = {0.f, 0.f, 0.f, 0.f};
    float racc1[4] = {0.f, 0.f, 0.f, 0.f};
    int g_run = -1;

    for (int t = t0; t < tend; ++t) {
        const int r0 = t * MTILE;

        __syncthreads();
        if (tid < MTILE) gid_s[tid] = batch_idx[r0 + tid];
        __syncthreads();

        #pragma unroll
        for (int base = 0; base < 8; base += 4) {
            float4 v[4];
            #pragma unroll
            for (int i = 0; i < 4; i++) {
                int j = tid + (base + i) * 256;
                int r = j >> 5, q = j & 31;
                v[i] = *(const float4*)(x + (size_t)(r0 + r) * D_NODE + q * 4);
            }
            #pragma unroll
            for (int i = 0; i < 4; i++) {
                int j = tid + (base + i) * 256;
                int r = j >> 5, q = j & 31;
                __nv_bfloat162 p0 = __float22bfloat162_rn(make_float2(v[i].x, v[i].y));
                __nv_bfloat162 p1 = __float22bfloat162_rn(make_float2(v[i].z, v[i].w));
                *(__nv_bfloat162*)&As[r * NKPAD + q * 4]     = p0;
                *(__nv_bfloat162*)&As[r * NKPAD + q * 4 + 2] = p1;
            }
        }
        __syncthreads();

        const int glo = gid_s[0];
        const int ghi = gid_s[MTILE - 1];

        float c[2][4][4];
        #pragma unroll
        for (int mf = 0; mf < 2; mf++)
            #pragma unroll
            for (int nf = 0; nf < 4; nf++)
                #pragma unroll
                for (int r = 0; r < 4; r++) c[mf][nf][r] = 0.f;

        #pragma unroll
        for (int ks = 0; ks < 8; ks++) {
            const uint32_t koff = (uint32_t)(ks * 32);
            uint32_t a[2][4];
            LDSM_X4(a[0][0], a[0][1], a[0][2], a[0][3], a_addr0 + koff);
            LDSM_X4(a[1][0], a[1][1], a[1][2], a[1][3], a_addr1 + koff);
            #pragma unroll
            for (int nfp = 0; nfp < 2; nfp++) {
                uint32_t b0, b1, b2, b3;
                LDSM_X4(b0, b1, b2, b3,
                        b_addr0 + (uint32_t)(nfp * 16 * NKPAD * 2) + koff);
                const int nf = 2 * nfp;
                MMA16816(c[0][nf][0], c[0][nf][1], c[0][nf][2], c[0][nf][3],
                         a[0][0], a[0][1], a[0][2], a[0][3], b0, b1);
                MMA16816(c[1][nf][0], c[1][nf][1], c[1][nf][2], c[1][nf][3],
                         a[1][0], a[1][1], a[1][2], a[1][3], b0, b1);
                MMA16816(c[0][nf+1][0], c[0][nf+1][1], c[0][nf+1][2], c[0][nf+1][3],
                         a[0][0], a[0][1], a[0][2], a[0][3], b2, b3);
                MMA16816(c[1][nf+1][0], c[1][nf+1][1], c[1][nf+1][2], c[1][nf+1][3],
                         a[1][0], a[1][1], a[1][2], a[1][3], b2, b3);
            }
        }

        #pragma unroll
        for (int nf = 0; nf < 4; nf++) {
            float b0 = bias_s[wn + nf * 8 + 2 * tig];
            float b1 = bias_s[wn + nf * 8 + 2 * tig + 1];
            #pragma unroll
            for (int mf = 0; mf < 2; mf++) {
                c[mf][nf][0] = fmaxf(c[mf][nf][0] + b0, 0.f);
                c[mf][nf][1] = fmaxf(c[mf][nf][1] + b1, 0.f);
                c[mf][nf][2] = fmaxf(c[mf][nf][2] + b0, 0.f);
                c[mf][nf][3] = fmaxf(c[mf][nf][3] + b1, 0.f);
            }
        }

        if (glo == ghi) {
            const int g = glo;
            if (g_run != g) { FLUSH_RACC(d_S_node, g_run); g_run = g; }
            #pragma unroll
            for (int nf = 0; nf < 4; nf++) {
                float s0 = c[0][nf][0] + c[0][nf][2] + c[1][nf][0] + c[1][nf][2];
                float s1 = c[0][nf][1] + c[0][nf][3] + c[1][nf][1] + c[1][nf][3];
                #pragma unroll
                for (int o = 4; o <= 16; o <<= 1) {
                    s0 += __shfl_xor_sync(0xffffffffu, s0, o);
                    s1 += __shfl_xor_sync(0xffffffffu, s1, o);
                }
                racc0[nf] += s0;
                racc1[nf] += s1;
            }
        } else {
            FLUSH_RACC(d_S_node, g_run);
            g_run = -1;
            const int gID = lane >> 2;
            int gr00 = gid_s[wm + gID];
            int gr01 = gid_s[wm + 16 + gID];
            int gr10 = gid_s[wm + gID + 8];
            int gr11 = gid_s[wm + 16 + gID + 8];
            for (int g = glo; g <= ghi; ++g) {
                #pragma unroll
                for (int nf = 0; nf < 4; nf++) {
                    float s0 = 0.f, s1 = 0.f;
                    if (gr00 == g) { s0 += c[0][nf][0]; s1 += c[0][nf][1]; }
                    if (gr10 == g) { s0 += c[0][nf][2]; s1 += c[0][nf][3]; }
                    if (gr01 == g) { s0 += c[1][nf][0]; s1 += c[1][nf][1]; }
                    if (gr11 == g) { s0 += c[1][nf][2]; s1 += c[1][nf][3]; }
                    #pragma unroll
                    for (int o = 4; o <= 16; o <<= 1) {
                        s0 += __shfl_xor_sync(0xffffffffu, s0, o);
                        s1 += __shfl_xor_sync(0xffffffffu, s1, o);
                    }
                    if (lane < 4) {
                        float* dst = &d_S_node[g * HDIM + nbase + wn + nf * 8 + 2 * lane];
                        atomicAdd(dst,     s0);
                        atomicAdd(dst + 1, s1);
                    }
                }
            }
        }
    }
    FLUSH_RACC(d_S_node, g_run);
}

// ---------------- launch #5: means -> layer-2 -> combine ------------------
__global__ void __launch_bounds__(256)
k_finalize(const float* __restrict__ Wn2, const float* __restrict__ bn2,
           const float* __restrict__ We2, const float* __restrict__ be2,
           const float* __restrict__ Wc,  const float* __restrict__ bc,
           float* __restrict__ out)
{
    __shared__ float mn[8][HDIM], me[8][HDIM], gr[8][HDIM];
    __shared__ int fn[8], fe[8];
    const int tid = threadIdx.x;
    const int gbase = blockIdx.x * 8;

    #pragma unroll
    for (int gg = 0; gg < 8; gg++) {
        int g = gbase + gg;
        int cn = d_cnt_node[g], ce = d_cnt_edge[g];
        if (tid == 0) { fn[gg] = cn; fe[gg] = ce; }
        mn[gg][tid] = (cn > 0) ? d_S_node[g * HDIM + tid] / (float)cn : 0.f;
        me[gg][tid] = (ce > 0) ? d_S_edge[g * HDIM + tid] / (float)ce : 0.f;
    }
    __syncthreads();

    float an[8], ae[8];
    #pragma unroll
    for (int gg = 0; gg < 8; gg++) { an[gg] = 0.f; ae[gg] = 0.f; }
    for (int j = 0; j < HDIM; j++) {
        float w1 = Wn2[j * HDIM + tid];
        float w2 = We2[j * HDIM + tid];
        #pragma unroll
        for (int gg = 0; gg < 8; gg++) {
            an[gg] += mn[gg][j] * w1;
            ae[gg] += me[gg][j] * w2;
        }
    }
    float b2n = bn2[tid], b2e = be2[tid];
    #pragma unroll
    for (int gg = 0; gg < 8; gg++) {
        float nr = (fn[gg] > 0) ? an[gg] + b2n : 0.f;
        float er = (fe[gg] > 0) ? ae[gg] + b2e : 0.f;
        gr[gg][tid] = nr + er;
    }
    __syncthreads();

    float ao[8];
    #pragma unroll
    for (int gg = 0; gg < 8; gg++) ao[gg] = 0.f;
    for (int j = 0; j < HDIM; j++) {
        float w = Wc[j * HDIM + tid];
        #pragma unroll
        for (int gg = 0; gg < 8; gg++) ao[gg] += gr[gg][j] * w;
    }
    float bcv = bc[tid];
    #pragma unroll
    for (int gg = 0; gg < 8; gg++)
        out[(gbase + gg) * HDIM + tid] = ao[gg] + bcv;
}

// ---------------- launch ----------------
extern "C" void kernel_launch(void* const* d_in, const int* in_sizes, int n_in,
                              void* d_out, int out_size)
{
    const float* x         = (const float*)d_in[0];
    const float* edge_attr = (const float*)d_in[1];
    const int*   batch_idx = (const int*)d_in[2];
    const int*   edge_src  = (const int*)d_in[3];
    const float* Wn1 = (const float*)d_in[4];
    const float* bn1 = (const float*)d_in[5];
    const float* Wn2 = (const float*)d_in[6];
    const float* bn2 = (const float*)d_in[7];
    const float* We1 = (const float*)d_in[8];
    const float* be1 = (const float*)d_in[9];
    const float* We2 = (const float*)d_in[10];
    const float* be2 = (const float*)d_in[11];
    const float* Wc  = (const float*)d_in[12];
    const float* bc  = (const float*)d_in[13];
    float* out = (float*)d_out;

    (void)in_sizes; (void)n_in; (void)out_size;

    cudaFuncSetAttribute(k_gemm_edge, cudaFuncAttributeMaxDynamicSharedMemorySize, E_SMEM);
    cudaFuncSetAttribute(k_gemm_node, cudaFuncAttributeMaxDynamicSharedMemorySize, SMEM_NODE);

    // zero scratch via memset nodes (not kernel launches)
    void* p;
    cudaGetSymbolAddress(&p, d_cnt_edge);  cudaMemsetAsync(p, 0, NGRAPH * sizeof(int));
    cudaGetSymbolAddress(&p, d_cursor);    cudaMemsetAsync(p, 0, NGRAPH * sizeof(int));
    cudaGetSymbolAddress(&p, d_S_node);    cudaMemsetAsync(p, 0, NGRAPH * HDIM * sizeof(float));
    cudaGetSymbolAddress(&p, d_S_edge);    cudaMemsetAsync(p, 0, NGRAPH * HDIM * sizeof(float));

    k_setup<<<577, 256>>>(Wn1, We1, batch_idx, edge_src);              // kernel #1
    k_scatter<<<SC_BLOCKS, 256>>>();                                   // #2
    k_gemm_edge<<<444, 256, E_SMEM>>>(edge_attr, be1);                 // #3
    k_gemm_node<<<592, 256, SMEM_NODE>>>(x, batch_idx, bn1);           // #4 (PROFILED)
    k_finalize<<<64, 256>>>(Wn2, bn2, We2, be2, Wc, bc, out);          // #5
}